// round 8
// baseline (speedup 1.0000x reference)
#include <cuda_runtime.h>
#include <math.h>

// Problem constants
#define PB 2
#define PL 2048
#define PD 1024
#define PH 16
#define PHD 64
#define PM (PB*PL)          // 4096
#define PN3 (3*PD)          // 3072
#define PZH (PB*PH)         // 32
#define OUT_ELEMS (PB*PL*PD)                     // 4194304
#define ATTN_ELEMS ((long long)PZH*PL*PL)        // 134217728

// Scratch (allocation-free rule: device globals)
__device__ float  g_q[PZH*PL*PHD];
__device__ float  g_k[PZH*PL*PHD];
__device__ float  g_v[PZH*PL*PHD];
__device__ float  g_ctx[PM*PD];
__device__ float2 g_stats[PZH*PL];
__device__ float  g_attn[134217728];   // fallback if attn not part of d_out

// ---------------------------------------------------------------------------
// helpers
// ---------------------------------------------------------------------------
__device__ __forceinline__ unsigned f2tf(float x){
    unsigned r; asm("cvt.rna.tf32.f32 %0, %1;" : "=r"(r) : "f"(x)); return r;
}
__device__ __forceinline__ void mma8(float* c, const unsigned* a, const unsigned* b){
    asm volatile("mma.sync.aligned.m16n8k8.row.col.f32.tf32.tf32.f32 "
        "{%0,%1,%2,%3}, {%4,%5,%6,%7}, {%8,%9}, {%0,%1,%2,%3};\n"
        : "+f"(c[0]),"+f"(c[1]),"+f"(c[2]),"+f"(c[3])
        : "r"(a[0]),"r"(a[1]),"r"(a[2]),"r"(a[3]), "r"(b[0]),"r"(b[1]));
}
__device__ __forceinline__ unsigned smem_u32(const void* p){
    return (unsigned)__cvta_generic_to_shared(p);
}
#define CP16(dst,src) asm volatile("cp.async.cg.shared.global [%0], [%1], 16;\n" :: "r"(dst), "l"(src))
#define CP_COMMIT()   asm volatile("cp.async.commit_group;\n")
#define CP_WAIT1()    asm volatile("cp.async.wait_group 1;\n")
#define CP_WAIT0()    asm volatile("cp.async.wait_group 0;\n")

// ---------------------------------------------------------------------------
// Generic TF32 GEMM, 128x128 tile, BK=16, cp.async double buffer, 256 thr.
// MODE 0: C = A@B + bias.   MODE 1: QKV scatter (no-transpose reshape).
// ---------------------------------------------------------------------------
template<int MODE>
__global__ void __launch_bounds__(256) gemm_tf32(
    const float* __restrict__ A, const float* __restrict__ B,
    const float* __restrict__ bias, float* __restrict__ C,
    int N, int K,
    float* __restrict__ qd, float* __restrict__ kd, float* __restrict__ vd)
{
    __shared__ float As[2][128][20];
    __shared__ float Bs[2][16][136];
    const int tid = threadIdx.x, lane = tid & 31, warp = tid >> 5;
    const int wm = warp >> 2, wn = warp & 3;
    const int g = lane >> 2, t4 = lane & 3;
    const int row0 = blockIdx.y * 128, col0 = blockIdx.x * 128;
    float acc[4][4][4] = {};

    const int iters = K / 16;
    {
        #pragma unroll
        for (int p = 0; p < 2; p++){
            int idx = tid + p*256; int r = idx >> 2, kc = (idx & 3) << 2;
            CP16(smem_u32(&As[0][r][kc]), &A[(long long)(row0+r)*K + kc]);
        }
        #pragma unroll
        for (int p = 0; p < 2; p++){
            int idx = tid + p*256; int r = idx >> 5, c = (idx & 31) << 2;
            CP16(smem_u32(&Bs[0][r][c]), &B[(long long)r*N + col0 + c]);
        }
        CP_COMMIT();
    }
    for (int it = 0; it < iters; ++it){
        if (it + 1 < iters){
            const int k0 = (it+1)*16, nb = (it+1)&1;
            #pragma unroll
            for (int p = 0; p < 2; p++){
                int idx = tid + p*256; int r = idx >> 2, kc = (idx & 3) << 2;
                CP16(smem_u32(&As[nb][r][kc]), &A[(long long)(row0+r)*K + k0 + kc]);
            }
            #pragma unroll
            for (int p = 0; p < 2; p++){
                int idx = tid + p*256; int r = idx >> 5, c = (idx & 31) << 2;
                CP16(smem_u32(&Bs[nb][r][c]), &B[(long long)(k0+r)*N + col0 + c]);
            }
        }
        CP_COMMIT();
        CP_WAIT1();
        __syncthreads();
        const int b = it & 1;
        #pragma unroll
        for (int ks = 0; ks < 2; ks++){
            unsigned af[4][4], bf[4][2];
            #pragma unroll
            for (int mt = 0; mt < 4; mt++){
                int r = wm*64 + mt*16 + g;
                af[mt][0] = f2tf(As[b][r  ][ks*8 + t4  ]);
                af[mt][1] = f2tf(As[b][r+8][ks*8 + t4  ]);
                af[mt][2] = f2tf(As[b][r  ][ks*8 + t4+4]);
                af[mt][3] = f2tf(As[b][r+8][ks*8 + t4+4]);
            }
            #pragma unroll
            for (int nt = 0; nt < 4; nt++){
                int c = wn*32 + nt*8 + g;
                bf[nt][0] = f2tf(Bs[b][ks*8 + t4  ][c]);
                bf[nt][1] = f2tf(Bs[b][ks*8 + t4+4][c]);
            }
            #pragma unroll
            for (int mt = 0; mt < 4; mt++)
                #pragma unroll
                for (int nt = 0; nt < 4; nt++)
                    mma8(acc[mt][nt], af[mt], bf[nt]);
        }
        __syncthreads();
    }
    #pragma unroll
    for (int mt = 0; mt < 4; mt++){
        #pragma unroll
        for (int nt = 0; nt < 4; nt++){
            const int r = row0 + wm*64 + mt*16 + g;
            const int c = col0 + wn*32 + nt*8 + t4*2;
            float bx = bias ? bias[c] : 0.f, by = bias ? bias[c+1] : 0.f;
            float v0 = acc[mt][nt][0] + bx, v1 = acc[mt][nt][1] + by;
            float v2 = acc[mt][nt][2] + bx, v3 = acc[mt][nt][3] + by;
            if (MODE == 0){
                float2 o0 = {v0, v1}, o1 = {v2, v3};
                *(float2*)&C[(long long)r*N + c]     = o0;
                *(float2*)&C[(long long)(r+8)*N + c] = o1;
            } else {
                const int sel = c >> 10, cd = c & 1023;
                const int d = cd & 63, csl = cd >> 6;
                float* dst = sel == 0 ? qd : (sel == 1 ? kd : vd);
                {
                    const int bb = r >> 11, lrow = r & 2047;
                    const int h = lrow >> 7, u = lrow & 127;
                    const int l2 = u*16 + csl;
                    long long off = ((long long)((bb*16 + h)*2048 + l2))*64 + d;
                    float2 o = {v0, v1}; *(float2*)&dst[off] = o;
                }
                {
                    const int r2 = r + 8;
                    const int bb = r2 >> 11, lrow = r2 & 2047;
                    const int h = lrow >> 7, u = lrow & 127;
                    const int l2 = u*16 + csl;
                    long long off = ((long long)((bb*16 + h)*2048 + l2))*64 + d;
                    float2 o = {v2, v3}; *(float2*)&dst[off] = o;
                }
            }
        }
    }
}

// ---------------------------------------------------------------------------
// FLASH PATH (attn NOT materialized): fused scores+softmax+attn@V.
// Grid (PL/128, PZH), 256 threads. Per iter: 64 kv rows.
// smem (dynamic): Qs[128][68] | Ks[64][68] | Vs[64][68] | Ps[128][68] (tf32)
// ---------------------------------------------------------------------------
__global__ void __launch_bounds__(256) flash_attn(
    const float* __restrict__ Qg, const float* __restrict__ Kg,
    const float* __restrict__ Vg, const float* __restrict__ mask,
    float* __restrict__ ctx)
{
    extern __shared__ float sm[];
    float*    Qs = sm;                         // 128*68
    float*    Ks = sm + 8704;                  // 64*68
    float*    Vs = sm + 13056;                 // 64*68
    unsigned* Ps = (unsigned*)(sm + 17408);    // 128*68 (tf32 bits)
    __shared__ float srs[128];

    const int z = blockIdx.y, row0 = blockIdx.x * 128;
    Qg += (long long)z * PL * PHD;
    Kg += (long long)z * PL * PHD;
    Vg += (long long)z * PL * PHD;

    const int tid = threadIdx.x, lane = tid & 31, warp = tid >> 5;
    const int wq = warp >> 1, wn = warp & 1;   // 4 row-strips x 2 col-strips
    const int g = lane >> 2, t4 = lane & 3;

    // prologue: Q tile + first K/V tiles
    #pragma unroll
    for (int p = 0; p < 8; p++){
        int idx = tid + p*256; int r = idx >> 4, c = (idx & 15) << 2;
        CP16(smem_u32(&Qs[r*68 + c]), &Qg[(long long)(row0+r)*PHD + c]);
    }
    #pragma unroll
    for (int p = 0; p < 4; p++){
        int idx = tid + p*256; int r = idx >> 4, c = (idx & 15) << 2;
        CP16(smem_u32(&Ks[r*68 + c]), &Kg[(long long)r*PHD + c]);
        CP16(smem_u32(&Vs[r*68 + c]), &Vg[(long long)r*PHD + c]);
    }
    CP_COMMIT();
    if (tid < 128) srs[tid] = 0.f;

    float acc[2][4][4] = {};     // ctx accumulator (unnormalized)
    float rs[2][2] = {};         // running row sums: [mt][row-half]
    const float scale = 0.03125f;

    for (int j = 0; j < PL/64; ++j){
        CP_WAIT0();
        __syncthreads();
        // ---- mma1: S_blk = Q @ K_blk^T (per warp 32x32) ----
        float acc1[2][4][4] = {};
        #pragma unroll
        for (int ks = 0; ks < 8; ks++){
            unsigned af[2][4], bf[4][2];
            #pragma unroll
            for (int mt = 0; mt < 2; mt++){
                int rq = wq*32 + mt*16 + g;
                af[mt][0] = f2tf(Qs[rq*68     + ks*8 + t4  ]);
                af[mt][1] = f2tf(Qs[(rq+8)*68 + ks*8 + t4  ]);
                af[mt][2] = f2tf(Qs[rq*68     + ks*8 + t4+4]);
                af[mt][3] = f2tf(Qs[(rq+8)*68 + ks*8 + t4+4]);
            }
            #pragma unroll
            for (int nt = 0; nt < 4; nt++){
                int kn = wn*32 + nt*8 + g;
                bf[nt][0] = f2tf(Ks[kn*68 + ks*8 + t4  ]);
                bf[nt][1] = f2tf(Ks[kn*68 + ks*8 + t4+4]);
            }
            #pragma unroll
            for (int mt = 0; mt < 2; mt++)
                #pragma unroll
                for (int nt = 0; nt < 4; nt++)
                    mma8(acc1[mt][nt], af[mt], bf[nt]);
        }
        __syncthreads();           // Ks fully consumed
        if (j + 1 < PL/64){
            const float* Kn = Kg + (long long)(j+1)*64*PHD;
            #pragma unroll
            for (int p = 0; p < 4; p++){
                int idx = tid + p*256; int r = idx >> 4, c = (idx & 15) << 2;
                CP16(smem_u32(&Ks[r*68 + c]), &Kn[(long long)r*PHD + c]);
            }
            CP_COMMIT();
        }
        // ---- mask * scale, exp, row sums, stage P (tf32 bits) ----
        #pragma unroll
        for (int mt = 0; mt < 2; mt++){
            const int rq = wq*32 + mt*16 + g;
            const int qr = row0 + rq;
            #pragma unroll
            for (int nt = 0; nt < 4; nt++){
                const int cc = wn*32 + nt*8 + t4*2;
                const int kc = j*64 + cc;
                float2 m0 = *(const float2*)&mask[(long long)qr*PL + kc];
                float2 m1 = *(const float2*)&mask[(long long)(qr+8)*PL + kc];
                float e0 = __expf(acc1[mt][nt][0]*scale*m0.x);
                float e1 = __expf(acc1[mt][nt][1]*scale*m0.y);
                float e2 = __expf(acc1[mt][nt][2]*scale*m1.x);
                float e3 = __expf(acc1[mt][nt][3]*scale*m1.y);
                rs[mt][0] += e0 + e1;
                rs[mt][1] += e2 + e3;
                uint2 u0 = {f2tf(e0), f2tf(e1)};
                uint2 u1 = {f2tf(e2), f2tf(e3)};
                *(uint2*)&Ps[rq*68 + cc]     = u0;
                *(uint2*)&Ps[(rq+8)*68 + cc] = u1;
            }
        }
        __syncthreads();           // Ps ready
        // ---- mma2: ctx += P_blk @ V_blk ----
        #pragma unroll
        for (int ks = 0; ks < 8; ks++){
            unsigned af[2][4], bf[4][2];
            #pragma unroll
            for (int mt = 0; mt < 2; mt++){
                int rq = wq*32 + mt*16 + g;
                af[mt][0] = Ps[rq*68     + ks*8 + t4  ];
                af[mt][1] = Ps[(rq+8)*68 + ks*8 + t4  ];
                af[mt][2] = Ps[rq*68     + ks*8 + t4+4];
                af[mt][3] = Ps[(rq+8)*68 + ks*8 + t4+4];
            }
            #pragma unroll
            for (int nt = 0; nt < 4; nt++){
                int cn = wn*32 + nt*8 + g;
                bf[nt][0] = f2tf(Vs[(ks*8 + t4  )*68 + cn]);
                bf[nt][1] = f2tf(Vs[(ks*8 + t4+4)*68 + cn]);
            }
            #pragma unroll
            for (int mt = 0; mt < 2; mt++)
                #pragma unroll
                for (int nt = 0; nt < 4; nt++)
                    mma8(acc[mt][nt], af[mt], bf[nt]);
        }
        __syncthreads();           // Vs fully consumed
        if (j + 1 < PL/64){
            const float* Vn = Vg + (long long)(j+1)*64*PHD;
            #pragma unroll
            for (int p = 0; p < 4; p++){
                int idx = tid + p*256; int r = idx >> 4, c = (idx & 15) << 2;
                CP16(smem_u32(&Vs[r*68 + c]), &Vn[(long long)r*PHD + c]);
            }
            CP_COMMIT();
        }
    }
    // ---- finalize row sums: reduce across t4 lanes, then across wn warps ----
    #pragma unroll
    for (int mt = 0; mt < 2; mt++)
        #pragma unroll
        for (int hh = 0; hh < 2; hh++){
            rs[mt][hh] += __shfl_xor_sync(0xffffffffu, rs[mt][hh], 1);
            rs[mt][hh] += __shfl_xor_sync(0xffffffffu, rs[mt][hh], 2);
        }
    if (t4 == 0){
        #pragma unroll
        for (int mt = 0; mt < 2; mt++){
            const int lr = wq*32 + mt*16 + g;
            atomicAdd(&srs[lr],   rs[mt][0]);
            atomicAdd(&srs[lr+8], rs[mt][1]);
        }
    }
    __syncthreads();
    // ---- epilogue: normalize, write ctx in merged [B,L,D] layout ----
    const int bb = z >> 4, h = z & 15;
    #pragma unroll
    for (int mt = 0; mt < 2; mt++){
        const int lr = wq*32 + mt*16 + g;
        const float inv0 = 1.f / srs[lr];
        const float inv1 = 1.f / srs[lr+8];
        #pragma unroll
        for (int nt = 0; nt < 4; nt++){
            const int d = wn*32 + nt*8 + t4*2;
            {
                const int l = row0 + lr;
                int crow = bb*PL + h*128 + (l >> 4);
                int ccol = (l & 15)*64 + d;
                float2 o = {acc[mt][nt][0]*inv0, acc[mt][nt][1]*inv0};
                *(float2*)&ctx[(long long)crow*PD + ccol] = o;
            }
            {
                const int l = row0 + lr + 8;
                int crow = bb*PL + h*128 + (l >> 4);
                int ccol = (l & 15)*64 + d;
                float2 o = {acc[mt][nt][2]*inv1, acc[mt][nt][3]*inv1};
                *(float2*)&ctx[(long long)crow*PD + ccol] = o;
            }
        }
    }
}

// ---------------------------------------------------------------------------
// ATTN-MATERIALIZING PATH (unchanged from R5, proven correct)
// ---------------------------------------------------------------------------
__global__ void __launch_bounds__(256) scores_tf32(
    const float* __restrict__ Q, const float* __restrict__ Kh,
    const float* __restrict__ mask, float* __restrict__ S)
{
    __shared__ float As[128][36];
    __shared__ float Bs[32][136];
    const int z = blockIdx.z;
    Q  += (long long)z * PL * PHD;
    Kh += (long long)z * PL * PHD;
    S  += (long long)z * PL * PL;
    const int tid = threadIdx.x, lane = tid & 31, warp = tid >> 5;
    const int wm = warp >> 2, wn = warp & 3;
    const int g = lane >> 2, t4 = lane & 3;
    const int row0 = blockIdx.y * 128, col0 = blockIdx.x * 128;
    float acc[4][4][4] = {};

    #pragma unroll
    for (int k0 = 0; k0 < PHD; k0 += 32){
        __syncthreads();
        #pragma unroll
        for (int p = 0; p < 4; p++){
            int idx = tid + p*256; int r = idx >> 3, kc = (idx & 7) << 2;
            float4 a4 = *(const float4*)&Q[(long long)(row0+r)*PHD + k0 + kc];
            *(float4*)&As[r][kc] = a4;
            float4 b4 = *(const float4*)&Kh[(long long)(col0+r)*PHD + k0 + kc];
            Bs[kc  ][r] = b4.x; Bs[kc+1][r] = b4.y;
            Bs[kc+2][r] = b4.z; Bs[kc+3][r] = b4.w;
        }
        __syncthreads();
        #pragma unroll
        for (int ks = 0; ks < 4; ks++){
            unsigned af[4][4], bf[4][2];
            #pragma unroll
            for (int mt = 0; mt < 4; mt++){
                int r = wm*64 + mt*16 + g;
                af[mt][0] = f2tf(As[r  ][ks*8 + t4  ]);
                af[mt][1] = f2tf(As[r+8][ks*8 + t4  ]);
                af[mt][2] = f2tf(As[r  ][ks*8 + t4+4]);
                af[mt][3] = f2tf(As[r+8][ks*8 + t4+4]);
            }
            #pragma unroll
            for (int nt = 0; nt < 4; nt++){
                int c = wn*32 + nt*8 + g;
                bf[nt][0] = f2tf(Bs[ks*8 + t4  ][c]);
                bf[nt][1] = f2tf(Bs[ks*8 + t4+4][c]);
            }
            #pragma unroll
            for (int mt = 0; mt < 4; mt++)
                #pragma unroll
                for (int nt = 0; nt < 4; nt++)
                    mma8(acc[mt][nt], af[mt], bf[nt]);
        }
    }
    const float scale = 0.03125f;
    #pragma unroll
    for (int mt = 0; mt < 4; mt++){
        #pragma unroll
        for (int nt = 0; nt < 4; nt++){
            const int r = row0 + wm*64 + mt*16 + g;
            const int c = col0 + wn*32 + nt*8 + t4*2;
            float2 m0 = *(const float2*)&mask[(long long)r*PL + c];
            float2 m1 = *(const float2*)&mask[(long long)(r+8)*PL + c];
            float2 o0 = {acc[mt][nt][0]*scale*m0.x, acc[mt][nt][1]*scale*m0.y};
            float2 o1 = {acc[mt][nt][2]*scale*m1.x, acc[mt][nt][3]*scale*m1.y};
            *(float2*)&S[(long long)r*PL + c]     = o0;
            *(float2*)&S[(long long)(r+8)*PL + c] = o1;
        }
    }
}

__global__ void __launch_bounds__(256) stats_kernel(
    const float* __restrict__ S, float2* __restrict__ st)
{
    const int row  = blockIdx.x * 8 + (threadIdx.x >> 5);
    const int lane = threadIdx.x & 31;
    const float4* r = (const float4*)(S + (long long)row * PL);
    float4 v[16];
    float m = -1e30f;
    #pragma unroll
    for (int i = 0; i < 16; i++){
        v[i] = r[i*32 + lane];
        m = fmaxf(m, fmaxf(fmaxf(v[i].x, v[i].y), fmaxf(v[i].z, v[i].w)));
    }
    #pragma unroll
    for (int s = 16; s > 0; s >>= 1) m = fmaxf(m, __shfl_xor_sync(0xffffffffu, m, s));
    float sum = 0.f;
    #pragma unroll
    for (int i = 0; i < 16; i++){
        sum += __expf(v[i].x - m) + __expf(v[i].y - m)
             + __expf(v[i].z - m) + __expf(v[i].w - m);
    }
    #pragma unroll
    for (int s = 16; s > 0; s >>= 1) sum += __shfl_xor_sync(0xffffffffu, sum, s);
    if (lane == 0){ float2 o = {m, 1.f/sum}; st[row] = o; }
}

__global__ void __launch_bounds__(256) ctx_fused(
    float* __restrict__ S, const float* __restrict__ V,
    const float2* __restrict__ st, float* __restrict__ ctx)
{
    __shared__ float Ap[128][36];
    __shared__ float Vs[2][32][68];
    __shared__ float smax[128], sinv[128];
    const int z = blockIdx.y, row0 = blockIdx.x * 128;
    S += (long long)z * PL * PL;
    V += (long long)z * PL * PHD;
    const int tid = threadIdx.x, lane = tid & 31, warp = tid >> 5;
    const int wm = warp >> 1, wn = warp & 1;
    const int g = lane >> 2, t4 = lane & 3;
    if (tid < 128){
        float2 t = st[z*PL + row0 + tid];
        smax[tid] = t.x; sinv[tid] = t.y;
    }
    float acc[2][4][4] = {};
    #pragma unroll
    for (int p = 0; p < 2; p++){
        int idx = tid + p*256; int r = idx >> 4, c = (idx & 15) << 2;
        CP16(smem_u32(&Vs[0][r][c]), &V[(long long)r*PHD + c]);
    }
    CP_COMMIT();
    __syncthreads();
    for (int it = 0; it < PL/32; ++it){
        const int k0 = it * 32;
        #pragma unroll
        for (int p = 0; p < 4; p++){
            int idx = tid + p*256; int r = idx >> 3, kc = (idx & 7) << 2;
            long long off = (long long)(row0 + r)*PL + k0 + kc;
            float4 s4 = *(const float4*)&S[off];
            float mm = smax[r], ii = sinv[r];
            float4 pq;
            pq.x = __expf(s4.x - mm)*ii; pq.y = __expf(s4.y - mm)*ii;
            pq.z = __expf(s4.z - mm)*ii; pq.w = __expf(s4.w - mm)*ii;
            *(float4*)&S[off] = pq;
            *(float4*)&Ap[r][kc] = pq;
        }
        if (it + 1 < PL/32){
            const int nb = (it+1)&1, nk = (it+1)*32;
            #pragma unroll
            for (int p = 0; p < 2; p++){
                int idx = tid + p*256; int r = idx >> 4, c = (idx & 15) << 2;
                CP16(smem_u32(&Vs[nb][r][c]), &V[(long long)(nk+r)*PHD + c]);
            }
        }
        CP_COMMIT();
        CP_WAIT1();
        __syncthreads();
        const int b = it & 1;
        #pragma unroll
        for (int ks = 0; ks < 4; ks++){
            unsigned af[2][4], bf[4][2];
            #pragma unroll
            for (int mt = 0; mt < 2; mt++){
                int r = wm*32 + mt*16 + g;
                af[mt][0] = f2tf(Ap[r  ][ks*8 + t4  ]);
                af[mt][1] = f2tf(Ap[r+8][ks*8 + t4  ]);
                af[mt][2] = f2tf(Ap[r  ][ks*8 + t4+4]);
                af[mt][3] = f2tf(Ap[r+8][ks*8 + t4+4]);
            }
            #pragma unroll
            for (int nt = 0; nt < 4; nt++){
                int c = wn*32 + nt*8 + g;
                bf[nt][0] = f2tf(Vs[b][ks*8 + t4  ][c]);
                bf[nt][1] = f2tf(Vs[b][ks*8 + t4+4][c]);
            }
            #pragma unroll
            for (int mt = 0; mt < 2; mt++)
                #pragma unroll
                for (int nt = 0; nt < 4; nt++)
                    mma8(acc[mt][nt], af[mt], bf[nt]);
        }
        __syncthreads();
    }
    const int bb = z >> 4, h = z & 15;
    #pragma unroll
    for (int mt = 0; mt < 2; mt++){
        #pragma unroll
        for (int nt = 0; nt < 4; nt++){
            const int l = row0 + wm*32 + mt*16 + g;
            const int d = wn*32 + nt*8 + t4*2;
            {
                int crow = bb*PL + h*128 + (l >> 4);
                int ccol = (l & 15)*64 + d;
                float2 o = {acc[mt][nt][0], acc[mt][nt][1]};
                *(float2*)&ctx[(long long)crow*PD + ccol] = o;
            }
            {
                int l2 = l + 8;
                int crow = bb*PL + h*128 + (l2 >> 4);
                int ccol = (l2 & 15)*64 + d;
                float2 o = {acc[mt][nt][2], acc[mt][nt][3]};
                *(float2*)&ctx[(long long)crow*PD + ccol] = o;
            }
        }
    }
}

// ---------------------------------------------------------------------------
extern "C" void kernel_launch(void* const* d_in, const int* in_sizes, int n_in,
                              void* d_out, int out_size)
{
    const float* x    = (const float*)d_in[0];
    const float* mask = (const float*)d_in[1];
    const float* Wqkv = (const float*)d_in[2];
    const float* bqkv = (const float*)d_in[3];
    const float* Wout = (const float*)d_in[4];
    const float* bout = (const float*)d_in[5];
    float* out = (float*)d_out;

    float *q, *k, *v, *ctx, *attn_scratch; float2* stats;
    cudaGetSymbolAddress((void**)&q,    g_q);
    cudaGetSymbolAddress((void**)&k,    g_k);
    cudaGetSymbolAddress((void**)&v,    g_v);
    cudaGetSymbolAddress((void**)&ctx,  g_ctx);
    cudaGetSymbolAddress((void**)&stats, g_stats);
    cudaGetSymbolAddress((void**)&attn_scratch, g_attn);

    const bool attn_in_out =
        ((long long)out_size >= (long long)OUT_ELEMS + ATTN_ELEMS);

    // 1) QKV projection + head split (fused epilogue, no-transpose reshape)
    {
        dim3 grd(PN3/128, PM/128);
        gemm_tf32<1><<<grd, 256>>>(x, Wqkv, bqkv, nullptr, PN3, PD, q, k, v);
    }
    if (attn_in_out){
        float* attn = out + OUT_ELEMS;
        dim3 gs(PL/128, PL/128, PZH);
        scores_tf32<<<gs, 256>>>(q, k, mask, attn);
        stats_kernel<<<PZH*PL/8, 256>>>(attn, stats);
        dim3 gc(PL/128, PZH);
        ctx_fused<<<gc, 256>>>(attn, v, stats, ctx);
    } else {
        // flash path: never materialize S/attn
        const int smem_bytes = (8704 + 4352 + 4352 + 8704) * 4;  // 104448
        cudaFuncSetAttribute(flash_attn,
                             cudaFuncAttributeMaxDynamicSharedMemorySize,
                             smem_bytes);
        dim3 gf(PL/128, PZH);
        flash_attn<<<gf, 256, smem_bytes>>>(q, k, v, mask, ctx);
    }
    // 5) output projection
    {
        dim3 grd(PD/128, PM/128);
        gemm_tf32<0><<<grd, 256>>>(ctx, Wout, bout, out, PD, PD,
                                   nullptr, nullptr, nullptr);
    }
}

// round 9
// speedup vs baseline: 1.2485x; 1.2485x over previous
#include <cuda_runtime.h>
#include <math.h>

// Problem constants
#define PB 2
#define PL 2048
#define PD 1024
#define PH 16
#define PHD 64
#define PM (PB*PL)          // 4096
#define PN3 (3*PD)          // 3072
#define PZH (PB*PH)         // 32
#define OUT_ELEMS (PB*PL*PD)                     // 4194304
#define ATTN_ELEMS ((long long)PZH*PL*PL)        // 134217728

// Scratch (allocation-free rule: device globals)
__device__ float  g_q[PZH*PL*PHD];
__device__ float  g_k[PZH*PL*PHD];
__device__ float  g_v[PZH*PL*PHD];
__device__ float  g_ctx[PM*PD];

// ---------------------------------------------------------------------------
// helpers
// ---------------------------------------------------------------------------
__device__ __forceinline__ unsigned f2tf(float x){
    unsigned r; asm("cvt.rna.tf32.f32 %0, %1;" : "=r"(r) : "f"(x)); return r;
}
__device__ __forceinline__ void mma8(float* c, const unsigned* a, const unsigned* b){
    asm volatile("mma.sync.aligned.m16n8k8.row.col.f32.tf32.tf32.f32 "
        "{%0,%1,%2,%3}, {%4,%5,%6,%7}, {%8,%9}, {%0,%1,%2,%3};\n"
        : "+f"(c[0]),"+f"(c[1]),"+f"(c[2]),"+f"(c[3])
        : "r"(a[0]),"r"(a[1]),"r"(a[2]),"r"(a[3]), "r"(b[0]),"r"(b[1]));
}
__device__ __forceinline__ unsigned smem_u32(const void* p){
    return (unsigned)__cvta_generic_to_shared(p);
}
#define CP16(dst,src) asm volatile("cp.async.cg.shared.global [%0], [%1], 16;\n" :: "r"(dst), "l"(src))
#define CP_COMMIT()   asm volatile("cp.async.commit_group;\n")
#define CP_WAIT1()    asm volatile("cp.async.wait_group 1;\n")
#define CP_WAIT0()    asm volatile("cp.async.wait_group 0;\n")

// ---------------------------------------------------------------------------
// Generic TF32 GEMM, 128x128 tile, BK=16, cp.async double buffer, 256 thr.
// MODE 0: C = A@B + bias.   MODE 1: QKV scatter (no-transpose reshape).
// ---------------------------------------------------------------------------
template<int MODE>
__global__ void __launch_bounds__(256) gemm_tf32(
    const float* __restrict__ A, const float* __restrict__ B,
    const float* __restrict__ bias, float* __restrict__ C,
    int N, int K,
    float* __restrict__ qd, float* __restrict__ kd, float* __restrict__ vd)
{
    __shared__ float As[2][128][20];
    __shared__ float Bs[2][16][136];
    const int tid = threadIdx.x, lane = tid & 31, warp = tid >> 5;
    const int wm = warp >> 2, wn = warp & 3;
    const int g = lane >> 2, t4 = lane & 3;
    const int row0 = blockIdx.y * 128, col0 = blockIdx.x * 128;
    float acc[4][4][4] = {};

    const int iters = K / 16;
    {
        #pragma unroll
        for (int p = 0; p < 2; p++){
            int idx = tid + p*256; int r = idx >> 2, kc = (idx & 3) << 2;
            CP16(smem_u32(&As[0][r][kc]), &A[(long long)(row0+r)*K + kc]);
        }
        #pragma unroll
        for (int p = 0; p < 2; p++){
            int idx = tid + p*256; int r = idx >> 5, c = (idx & 31) << 2;
            CP16(smem_u32(&Bs[0][r][c]), &B[(long long)r*N + col0 + c]);
        }
        CP_COMMIT();
    }
    for (int it = 0; it < iters; ++it){
        if (it + 1 < iters){
            const int k0 = (it+1)*16, nb = (it+1)&1;
            #pragma unroll
            for (int p = 0; p < 2; p++){
                int idx = tid + p*256; int r = idx >> 2, kc = (idx & 3) << 2;
                CP16(smem_u32(&As[nb][r][kc]), &A[(long long)(row0+r)*K + k0 + kc]);
            }
            #pragma unroll
            for (int p = 0; p < 2; p++){
                int idx = tid + p*256; int r = idx >> 5, c = (idx & 31) << 2;
                CP16(smem_u32(&Bs[nb][r][c]), &B[(long long)(k0+r)*N + col0 + c]);
            }
        }
        CP_COMMIT();
        CP_WAIT1();
        __syncthreads();
        const int b = it & 1;
        #pragma unroll
        for (int ks = 0; ks < 2; ks++){
            unsigned af[4][4], bf[4][2];
            #pragma unroll
            for (int mt = 0; mt < 4; mt++){
                int r = wm*64 + mt*16 + g;
                af[mt][0] = f2tf(As[b][r  ][ks*8 + t4  ]);
                af[mt][1] = f2tf(As[b][r+8][ks*8 + t4  ]);
                af[mt][2] = f2tf(As[b][r  ][ks*8 + t4+4]);
                af[mt][3] = f2tf(As[b][r+8][ks*8 + t4+4]);
            }
            #pragma unroll
            for (int nt = 0; nt < 4; nt++){
                int c = wn*32 + nt*8 + g;
                bf[nt][0] = f2tf(Bs[b][ks*8 + t4  ][c]);
                bf[nt][1] = f2tf(Bs[b][ks*8 + t4+4][c]);
            }
            #pragma unroll
            for (int mt = 0; mt < 4; mt++)
                #pragma unroll
                for (int nt = 0; nt < 4; nt++)
                    mma8(acc[mt][nt], af[mt], bf[nt]);
        }
        __syncthreads();
    }
    #pragma unroll
    for (int mt = 0; mt < 4; mt++){
        #pragma unroll
        for (int nt = 0; nt < 4; nt++){
            const int r = row0 + wm*64 + mt*16 + g;
            const int c = col0 + wn*32 + nt*8 + t4*2;
            float bx = bias ? bias[c] : 0.f, by = bias ? bias[c+1] : 0.f;
            float v0 = acc[mt][nt][0] + bx, v1 = acc[mt][nt][1] + by;
            float v2 = acc[mt][nt][2] + bx, v3 = acc[mt][nt][3] + by;
            if (MODE == 0){
                float2 o0 = {v0, v1}, o1 = {v2, v3};
                *(float2*)&C[(long long)r*N + c]     = o0;
                *(float2*)&C[(long long)(r+8)*N + c] = o1;
            } else {
                const int sel = c >> 10, cd = c & 1023;
                const int d = cd & 63, csl = cd >> 6;
                float* dst = sel == 0 ? qd : (sel == 1 ? kd : vd);
                {
                    const int bb = r >> 11, lrow = r & 2047;
                    const int h = lrow >> 7, u = lrow & 127;
                    const int l2 = u*16 + csl;
                    long long off = ((long long)((bb*16 + h)*2048 + l2))*64 + d;
                    float2 o = {v0, v1}; *(float2*)&dst[off] = o;
                }
                {
                    const int r2 = r + 8;
                    const int bb = r2 >> 11, lrow = r2 & 2047;
                    const int h = lrow >> 7, u = lrow & 127;
                    const int l2 = u*16 + csl;
                    long long off = ((long long)((bb*16 + h)*2048 + l2))*64 + d;
                    float2 o = {v2, v3}; *(float2*)&dst[off] = o;
                }
            }
        }
    }
}

// ---------------------------------------------------------------------------
// Two-phase flash attention WITH attn materialization.
// Phase 1: row sums of exp(scale*S*mask)  (compute only, no writes)
// Phase 2: recompute S, write normalized attn to gmem, accumulate ctx=P@V.
// Grid (PL/128, PZH), 256 threads; 64 kv rows per iteration.
// smem: Qs[128][68] | Ks[64][68] | Vs[64][68] | Ps[128][68] (tf32 bits)
// ---------------------------------------------------------------------------
__global__ void __launch_bounds__(256) flash2_attn(
    const float* __restrict__ Qg, const float* __restrict__ Kg,
    const float* __restrict__ Vg, const float* __restrict__ mask,
    float* __restrict__ attn, float* __restrict__ ctx)
{
    extern __shared__ float sm[];
    float*    Qs = sm;                         // 128*68
    float*    Ks = sm + 8704;                  // 64*68
    float*    Vs = sm + 13056;                 // 64*68
    unsigned* Ps = (unsigned*)(sm + 17408);    // 128*68 (tf32 bits)
    __shared__ float srs[128];

    const int z = blockIdx.y, row0 = blockIdx.x * 128;
    Qg += (long long)z * PL * PHD;
    Kg += (long long)z * PL * PHD;
    Vg += (long long)z * PL * PHD;
    attn += (long long)z * PL * PL;

    const int tid = threadIdx.x, lane = tid & 31, warp = tid >> 5;
    const int wq = warp >> 1, wn = warp & 1;   // 4 row-strips x 2 col-strips
    const int g = lane >> 2, t4 = lane & 3;
    const float scale = 0.03125f;

    // prologue: Q tile + first K tile
    #pragma unroll
    for (int p = 0; p < 8; p++){
        int idx = tid + p*256; int r = idx >> 4, c = (idx & 15) << 2;
        CP16(smem_u32(&Qs[r*68 + c]), &Qg[(long long)(row0+r)*PHD + c]);
    }
    #pragma unroll
    for (int p = 0; p < 4; p++){
        int idx = tid + p*256; int r = idx >> 4, c = (idx & 15) << 2;
        CP16(smem_u32(&Ks[r*68 + c]), &Kg[(long long)r*PHD + c]);
    }
    CP_COMMIT();
    if (tid < 128) srs[tid] = 0.f;

    float rs[2][2] = {};

    // ================= PHASE 1: row sums =================
    for (int j = 0; j < PL/64; ++j){
        CP_WAIT0();
        __syncthreads();
        float acc1[2][4][4] = {};
        #pragma unroll
        for (int ks = 0; ks < 8; ks++){
            unsigned af[2][4], bf[4][2];
            #pragma unroll
            for (int mt = 0; mt < 2; mt++){
                int rq = wq*32 + mt*16 + g;
                af[mt][0] = f2tf(Qs[rq*68     + ks*8 + t4  ]);
                af[mt][1] = f2tf(Qs[(rq+8)*68 + ks*8 + t4  ]);
                af[mt][2] = f2tf(Qs[rq*68     + ks*8 + t4+4]);
                af[mt][3] = f2tf(Qs[(rq+8)*68 + ks*8 + t4+4]);
            }
            #pragma unroll
            for (int nt = 0; nt < 4; nt++){
                int kn = wn*32 + nt*8 + g;
                bf[nt][0] = f2tf(Ks[kn*68 + ks*8 + t4  ]);
                bf[nt][1] = f2tf(Ks[kn*68 + ks*8 + t4+4]);
            }
            #pragma unroll
            for (int mt = 0; mt < 2; mt++)
                #pragma unroll
                for (int nt = 0; nt < 4; nt++)
                    mma8(acc1[mt][nt], af[mt], bf[nt]);
        }
        __syncthreads();           // Ks consumed
        if (j + 1 < PL/64){
            const float* Kn = Kg + (long long)(j+1)*64*PHD;
            #pragma unroll
            for (int p = 0; p < 4; p++){
                int idx = tid + p*256; int r = idx >> 4, c = (idx & 15) << 2;
                CP16(smem_u32(&Ks[r*68 + c]), &Kn[(long long)r*PHD + c]);
            }
        } else {
            // stage K0 + V0 for phase 2
            #pragma unroll
            for (int p = 0; p < 4; p++){
                int idx = tid + p*256; int r = idx >> 4, c = (idx & 15) << 2;
                CP16(smem_u32(&Ks[r*68 + c]), &Kg[(long long)r*PHD + c]);
                CP16(smem_u32(&Vs[r*68 + c]), &Vg[(long long)r*PHD + c]);
            }
        }
        CP_COMMIT();
        #pragma unroll
        for (int mt = 0; mt < 2; mt++){
            const int qr = row0 + wq*32 + mt*16 + g;
            #pragma unroll
            for (int nt = 0; nt < 4; nt++){
                const int kc = j*64 + wn*32 + nt*8 + t4*2;
                float2 m0 = *(const float2*)&mask[(long long)qr*PL + kc];
                float2 m1 = *(const float2*)&mask[(long long)(qr+8)*PL + kc];
                rs[mt][0] += __expf(acc1[mt][nt][0]*scale*m0.x)
                           + __expf(acc1[mt][nt][1]*scale*m0.y);
                rs[mt][1] += __expf(acc1[mt][nt][2]*scale*m1.x)
                           + __expf(acc1[mt][nt][3]*scale*m1.y);
            }
        }
    }
    // reduce row sums: across t4 lanes (xor 1,2), then across wn warps (smem)
    #pragma unroll
    for (int mt = 0; mt < 2; mt++)
        #pragma unroll
        for (int hh = 0; hh < 2; hh++){
            rs[mt][hh] += __shfl_xor_sync(0xffffffffu, rs[mt][hh], 1);
            rs[mt][hh] += __shfl_xor_sync(0xffffffffu, rs[mt][hh], 2);
        }
    if (t4 == 0){
        #pragma unroll
        for (int mt = 0; mt < 2; mt++){
            const int lr = wq*32 + mt*16 + g;
            atomicAdd(&srs[lr],   rs[mt][0]);
            atomicAdd(&srs[lr+8], rs[mt][1]);
        }
    }
    __syncthreads();
    float inv[2][2];
    #pragma unroll
    for (int mt = 0; mt < 2; mt++){
        const int lr = wq*32 + mt*16 + g;
        inv[mt][0] = 1.f / srs[lr];
        inv[mt][1] = 1.f / srs[lr+8];
    }

    // ================= PHASE 2: attn write + ctx =================
    float acc[2][4][4] = {};
    for (int j = 0; j < PL/64; ++j){
        CP_WAIT0();
        __syncthreads();
        float acc1[2][4][4] = {};
        #pragma unroll
        for (int ks = 0; ks < 8; ks++){
            unsigned af[2][4], bf[4][2];
            #pragma unroll
            for (int mt = 0; mt < 2; mt++){
                int rq = wq*32 + mt*16 + g;
                af[mt][0] = f2tf(Qs[rq*68     + ks*8 + t4  ]);
                af[mt][1] = f2tf(Qs[(rq+8)*68 + ks*8 + t4  ]);
                af[mt][2] = f2tf(Qs[rq*68     + ks*8 + t4+4]);
                af[mt][3] = f2tf(Qs[(rq+8)*68 + ks*8 + t4+4]);
            }
            #pragma unroll
            for (int nt = 0; nt < 4; nt++){
                int kn = wn*32 + nt*8 + g;
                bf[nt][0] = f2tf(Ks[kn*68 + ks*8 + t4  ]);
                bf[nt][1] = f2tf(Ks[kn*68 + ks*8 + t4+4]);
            }
            #pragma unroll
            for (int mt = 0; mt < 2; mt++)
                #pragma unroll
                for (int nt = 0; nt < 4; nt++)
                    mma8(acc1[mt][nt], af[mt], bf[nt]);
        }
        __syncthreads();           // Ks consumed
        if (j + 1 < PL/64){
            const float* Kn = Kg + (long long)(j+1)*64*PHD;
            #pragma unroll
            for (int p = 0; p < 4; p++){
                int idx = tid + p*256; int r = idx >> 4, c = (idx & 15) << 2;
                CP16(smem_u32(&Ks[r*68 + c]), &Kn[(long long)r*PHD + c]);
            }
            CP_COMMIT();
        }
        // normalized P: write attn to gmem + stage tf32 into Ps
        #pragma unroll
        for (int mt = 0; mt < 2; mt++){
            const int rq = wq*32 + mt*16 + g;
            const int qr = row0 + rq;
            #pragma unroll
            for (int nt = 0; nt < 4; nt++){
                const int cc = wn*32 + nt*8 + t4*2;
                const int kc = j*64 + cc;
                float2 m0 = *(const float2*)&mask[(long long)qr*PL + kc];
                float2 m1 = *(const float2*)&mask[(long long)(qr+8)*PL + kc];
                float p0 = __expf(acc1[mt][nt][0]*scale*m0.x)*inv[mt][0];
                float p1 = __expf(acc1[mt][nt][1]*scale*m0.y)*inv[mt][0];
                float p2 = __expf(acc1[mt][nt][2]*scale*m1.x)*inv[mt][1];
                float p3 = __expf(acc1[mt][nt][3]*scale*m1.y)*inv[mt][1];
                float2 o0 = {p0, p1}, o1 = {p2, p3};
                *(float2*)&attn[(long long)qr*PL + kc]     = o0;
                *(float2*)&attn[(long long)(qr+8)*PL + kc] = o1;
                uint2 u0 = {f2tf(p0), f2tf(p1)};
                uint2 u1 = {f2tf(p2), f2tf(p3)};
                *(uint2*)&Ps[rq*68 + cc]     = u0;
                *(uint2*)&Ps[(rq+8)*68 + cc] = u1;
            }
        }
        __syncthreads();           // Ps ready
        // ctx += P @ V
        #pragma unroll
        for (int ks = 0; ks < 8; ks++){
            unsigned af[2][4], bf[4][2];
            #pragma unroll
            for (int mt = 0; mt < 2; mt++){
                int rq = wq*32 + mt*16 + g;
                af[mt][0] = Ps[rq*68     + ks*8 + t4  ];
                af[mt][1] = Ps[(rq+8)*68 + ks*8 + t4  ];
                af[mt][2] = Ps[rq*68     + ks*8 + t4+4];
                af[mt][3] = Ps[(rq+8)*68 + ks*8 + t4+4];
            }
            #pragma unroll
            for (int nt = 0; nt < 4; nt++){
                int cn = wn*32 + nt*8 + g;
                bf[nt][0] = f2tf(Vs[(ks*8 + t4  )*68 + cn]);
                bf[nt][1] = f2tf(Vs[(ks*8 + t4+4)*68 + cn]);
            }
            #pragma unroll
            for (int mt = 0; mt < 2; mt++)
                #pragma unroll
                for (int nt = 0; nt < 4; nt++)
                    mma8(acc[mt][nt], af[mt], bf[nt]);
        }
        __syncthreads();           // Vs consumed
        if (j + 1 < PL/64){
            const float* Vn = Vg + (long long)(j+1)*64*PHD;
            #pragma unroll
            for (int p = 0; p < 4; p++){
                int idx = tid + p*256; int r = idx >> 4, c = (idx & 15) << 2;
                CP16(smem_u32(&Vs[r*68 + c]), &Vn[(long long)r*PHD + c]);
            }
            CP_COMMIT();
        }
    }
    // epilogue: ctx already normalized; write in merged [B,L,D] layout
    const int bb = z >> 4, h = z & 15;
    #pragma unroll
    for (int mt = 0; mt < 2; mt++){
        #pragma unroll
        for (int nt = 0; nt < 4; nt++){
            const int lr = wq*32 + mt*16 + g;
            const int d = wn*32 + nt*8 + t4*2;
            {
                const int l = row0 + lr;
                int crow = bb*PL + h*128 + (l >> 4);
                int ccol = (l & 15)*64 + d;
                float2 o = {acc[mt][nt][0], acc[mt][nt][1]};
                *(float2*)&ctx[(long long)crow*PD + ccol] = o;
            }
            {
                const int l = row0 + lr + 8;
                int crow = bb*PL + h*128 + (l >> 4);
                int ccol = (l & 15)*64 + d;
                float2 o = {acc[mt][nt][2], acc[mt][nt][3]};
                *(float2*)&ctx[(long long)crow*PD + ccol] = o;
            }
        }
    }
}

// ---------------------------------------------------------------------------
extern "C" void kernel_launch(void* const* d_in, const int* in_sizes, int n_in,
                              void* d_out, int out_size)
{
    const float* x    = (const float*)d_in[0];
    const float* mask = (const float*)d_in[1];
    const float* Wqkv = (const float*)d_in[2];
    const float* bqkv = (const float*)d_in[3];
    const float* Wout = (const float*)d_in[4];
    const float* bout = (const float*)d_in[5];
    float* out = (float*)d_out;

    float *q, *k, *v, *ctx;
    cudaGetSymbolAddress((void**)&q,   g_q);
    cudaGetSymbolAddress((void**)&k,   g_k);
    cudaGetSymbolAddress((void**)&v,   g_v);
    cudaGetSymbolAddress((void**)&ctx, g_ctx);

    // attn lives in d_out right after out (verified live in R5-R8)
    float* attn = out + OUT_ELEMS;

    // 1) QKV projection + head split (fused epilogue, no-transpose reshape)
    {
        dim3 grd(PN3/128, PM/128);
        gemm_tf32<1><<<grd, 256>>>(x, Wqkv, bqkv, nullptr, PN3, PD, q, k, v);
    }
    // 2) two-phase flash: row sums, then attn write + ctx accumulate
    {
        const int smem_bytes = (8704 + 4352 + 4352 + 8704) * 4;  // 104448
        cudaFuncSetAttribute(flash2_attn,
                             cudaFuncAttributeMaxDynamicSharedMemorySize,
                             smem_bytes);
        dim3 gf(PL/128, PZH);
        flash2_attn<<<gf, 256, smem_bytes>>>(q, k, v, mask, attn, ctx);
    }
    // 3) output projection
    {
        dim3 grd(PD/128, PM/128);
        gemm_tf32<0><<<grd, 256>>>(ctx, Wout, bout, out, PD, PD,
                                   nullptr, nullptr, nullptr);
    }
}

// round 10
// speedup vs baseline: 1.2921x; 1.0349x over previous
#include <cuda_runtime.h>
#include <math.h>

// Problem constants
#define PB 2
#define PL 2048
#define PD 1024
#define PH 16
#define PHD 64
#define PM (PB*PL)          // 4096
#define PN3 (3*PD)          // 3072
#define PZH (PB*PH)         // 32
#define OUT_ELEMS (PB*PL*PD)                     // 4194304
#define ATTN_ELEMS ((long long)PZH*PL*PL)        // 134217728

// Scratch (allocation-free rule: device globals). tf32-bit buffers are unsigned.
__device__ unsigned g_xb[PM*PD];          // X as tf32 bits
__device__ unsigned g_wqkvb[PD*PN3];      // Wqkv as tf32 bits
__device__ unsigned g_woutb[PD*PD];       // Wout as tf32 bits
__device__ unsigned g_q[PZH*PL*PHD];      // q as tf32 bits
__device__ unsigned g_k[PZH*PL*PHD];
__device__ unsigned g_v[PZH*PL*PHD];
__device__ unsigned g_ctx[PM*PD];         // ctx as tf32 bits

// ---------------------------------------------------------------------------
// helpers
// ---------------------------------------------------------------------------
__device__ __forceinline__ unsigned f2tf(float x){
    unsigned r; asm("cvt.rna.tf32.f32 %0, %1;" : "=r"(r) : "f"(x)); return r;
}
__device__ __forceinline__ void mma8(float* c, const unsigned* a, const unsigned* b){
    asm volatile("mma.sync.aligned.m16n8k8.row.col.f32.tf32.tf32.f32 "
        "{%0,%1,%2,%3}, {%4,%5,%6,%7}, {%8,%9}, {%0,%1,%2,%3};\n"
        : "+f"(c[0]),"+f"(c[1]),"+f"(c[2]),"+f"(c[3])
        : "r"(a[0]),"r"(a[1]),"r"(a[2]),"r"(a[3]), "r"(b[0]),"r"(b[1]));
}
__device__ __forceinline__ unsigned smem_u32(const void* p){
    return (unsigned)__cvta_generic_to_shared(p);
}
#define CP16(dst,src) asm volatile("cp.async.cg.shared.global [%0], [%1], 16;\n" :: "r"(dst), "l"(src))
#define CP_COMMIT()   asm volatile("cp.async.commit_group;\n")
#define CP_WAIT1()    asm volatile("cp.async.wait_group 1;\n")
#define CP_WAIT0()    asm volatile("cp.async.wait_group 0;\n")

// ---------------------------------------------------------------------------
// Elementwise fp32 -> tf32-bits conversion (vectorized)
// ---------------------------------------------------------------------------
__global__ void __launch_bounds__(256) cvt_tf32_kernel(
    const float4* __restrict__ in, uint4* __restrict__ out, int n4)
{
    int i = blockIdx.x * 256 + threadIdx.x;
    if (i < n4){
        float4 v = in[i];
        uint4 o = {f2tf(v.x), f2tf(v.y), f2tf(v.z), f2tf(v.w)};
        out[i] = o;
    }
}

// ---------------------------------------------------------------------------
// TF32 GEMM on pre-converted tf32-bit operands. 128x128 tile, BK=16,
// cp.async double buffer, 256 threads. NO cvt in the inner loop.
// MODE 0: C(out float) = A@B + bias.
// MODE 1: QKV scatter into tf32-bit q/k/v (no-transpose reshape), +bias.
// ---------------------------------------------------------------------------
template<int MODE>
__global__ void __launch_bounds__(256) gemm_tf32(
    const unsigned* __restrict__ A, const unsigned* __restrict__ B,
    const float* __restrict__ bias, float* __restrict__ C,
    int N, int K,
    unsigned* __restrict__ qd, unsigned* __restrict__ kd, unsigned* __restrict__ vd)
{
    __shared__ unsigned As[2][128][20];
    __shared__ unsigned Bs[2][16][136];
    const int tid = threadIdx.x, lane = tid & 31, warp = tid >> 5;
    const int wm = warp >> 2, wn = warp & 3;
    const int g = lane >> 2, t4 = lane & 3;
    const int row0 = blockIdx.y * 128, col0 = blockIdx.x * 128;
    float acc[4][4][4] = {};

    const int iters = K / 16;
    {
        #pragma unroll
        for (int p = 0; p < 2; p++){
            int idx = tid + p*256; int r = idx >> 2, kc = (idx & 3) << 2;
            CP16(smem_u32(&As[0][r][kc]), &A[(long long)(row0+r)*K + kc]);
        }
        #pragma unroll
        for (int p = 0; p < 2; p++){
            int idx = tid + p*256; int r = idx >> 5, c = (idx & 31) << 2;
            CP16(smem_u32(&Bs[0][r][c]), &B[(long long)r*N + col0 + c]);
        }
        CP_COMMIT();
    }
    for (int it = 0; it < iters; ++it){
        if (it + 1 < iters){
            const int k0 = (it+1)*16, nb = (it+1)&1;
            #pragma unroll
            for (int p = 0; p < 2; p++){
                int idx = tid + p*256; int r = idx >> 2, kc = (idx & 3) << 2;
                CP16(smem_u32(&As[nb][r][kc]), &A[(long long)(row0+r)*K + k0 + kc]);
            }
            #pragma unroll
            for (int p = 0; p < 2; p++){
                int idx = tid + p*256; int r = idx >> 5, c = (idx & 31) << 2;
                CP16(smem_u32(&Bs[nb][r][c]), &B[(long long)(k0+r)*N + col0 + c]);
            }
        }
        CP_COMMIT();
        CP_WAIT1();
        __syncthreads();
        const int b = it & 1;
        #pragma unroll
        for (int ks = 0; ks < 2; ks++){
            unsigned af[4][4], bf[4][2];
            #pragma unroll
            for (int mt = 0; mt < 4; mt++){
                int r = wm*64 + mt*16 + g;
                af[mt][0] = As[b][r  ][ks*8 + t4  ];
                af[mt][1] = As[b][r+8][ks*8 + t4  ];
                af[mt][2] = As[b][r  ][ks*8 + t4+4];
                af[mt][3] = As[b][r+8][ks*8 + t4+4];
            }
            #pragma unroll
            for (int nt = 0; nt < 4; nt++){
                int c = wn*32 + nt*8 + g;
                bf[nt][0] = Bs[b][ks*8 + t4  ][c];
                bf[nt][1] = Bs[b][ks*8 + t4+4][c];
            }
            #pragma unroll
            for (int mt = 0; mt < 4; mt++)
                #pragma unroll
                for (int nt = 0; nt < 4; nt++)
                    mma8(acc[mt][nt], af[mt], bf[nt]);
        }
        __syncthreads();
    }
    #pragma unroll
    for (int mt = 0; mt < 4; mt++){
        #pragma unroll
        for (int nt = 0; nt < 4; nt++){
            const int r = row0 + wm*64 + mt*16 + g;
            const int c = col0 + wn*32 + nt*8 + t4*2;
            float bx = bias ? bias[c] : 0.f, by = bias ? bias[c+1] : 0.f;
            float v0 = acc[mt][nt][0] + bx, v1 = acc[mt][nt][1] + by;
            float v2 = acc[mt][nt][2] + bx, v3 = acc[mt][nt][3] + by;
            if (MODE == 0){
                float2 o0 = {v0, v1}, o1 = {v2, v3};
                *(float2*)&C[(long long)r*N + c]     = o0;
                *(float2*)&C[(long long)(r+8)*N + c] = o1;
            } else {
                const int sel = c >> 10, cd = c & 1023;
                const int d = cd & 63, csl = cd >> 6;
                unsigned* dst = sel == 0 ? qd : (sel == 1 ? kd : vd);
                {
                    const int bb = r >> 11, lrow = r & 2047;
                    const int h = lrow >> 7, u = lrow & 127;
                    const int l2 = u*16 + csl;
                    long long off = ((long long)((bb*16 + h)*2048 + l2))*64 + d;
                    uint2 o = {f2tf(v0), f2tf(v1)}; *(uint2*)&dst[off] = o;
                }
                {
                    const int r2 = r + 8;
                    const int bb = r2 >> 11, lrow = r2 & 2047;
                    const int h = lrow >> 7, u = lrow & 127;
                    const int l2 = u*16 + csl;
                    long long off = ((long long)((bb*16 + h)*2048 + l2))*64 + d;
                    uint2 o = {f2tf(v2), f2tf(v3)}; *(uint2*)&dst[off] = o;
                }
            }
        }
    }
}

// ---------------------------------------------------------------------------
// Two-phase flash attention WITH attn materialization; q/k/v are tf32 bits.
// Phase 1: row sums of exp(scale*S*mask)  (compute only, no writes)
// Phase 2: recompute S, write normalized attn to gmem, accumulate ctx=P@V,
//          store ctx as tf32 bits (consumed only by the output GEMM).
// Grid (PL/128, PZH), 256 threads; 64 kv rows per iteration. 2 CTAs/SM.
// smem: Qs[128][68] | Ks[64][68] | Vs[64][68] | Ps[128][68]
// ---------------------------------------------------------------------------
__global__ void __launch_bounds__(256, 2) flash2_attn(
    const unsigned* __restrict__ Qg, const unsigned* __restrict__ Kg,
    const unsigned* __restrict__ Vg, const float* __restrict__ mask,
    float* __restrict__ attn, unsigned* __restrict__ ctx)
{
    extern __shared__ unsigned sm[];
    unsigned* Qs = sm;                         // 128*68
    unsigned* Ks = sm + 8704;                  // 64*68
    unsigned* Vs = sm + 13056;                 // 64*68
    unsigned* Ps = sm + 17408;                 // 128*68
    __shared__ float srs[128];

    const int z = blockIdx.y, row0 = blockIdx.x * 128;
    Qg += (long long)z * PL * PHD;
    Kg += (long long)z * PL * PHD;
    Vg += (long long)z * PL * PHD;
    attn += (long long)z * PL * PL;

    const int tid = threadIdx.x, lane = tid & 31, warp = tid >> 5;
    const int wq = warp >> 1, wn = warp & 1;   // 4 row-strips x 2 col-strips
    const int g = lane >> 2, t4 = lane & 3;
    const float scale = 0.03125f;

    // prologue: Q tile + first K tile
    #pragma unroll
    for (int p = 0; p < 8; p++){
        int idx = tid + p*256; int r = idx >> 4, c = (idx & 15) << 2;
        CP16(smem_u32(&Qs[r*68 + c]), &Qg[(long long)(row0+r)*PHD + c]);
    }
    #pragma unroll
    for (int p = 0; p < 4; p++){
        int idx = tid + p*256; int r = idx >> 4, c = (idx & 15) << 2;
        CP16(smem_u32(&Ks[r*68 + c]), &Kg[(long long)r*PHD + c]);
    }
    CP_COMMIT();
    if (tid < 128) srs[tid] = 0.f;

    float rs[2][2] = {};

    // ================= PHASE 1: row sums =================
    for (int j = 0; j < PL/64; ++j){
        CP_WAIT0();
        __syncthreads();
        float acc1[2][4][4] = {};
        #pragma unroll
        for (int ks = 0; ks < 8; ks++){
            unsigned af[2][4], bf[4][2];
            #pragma unroll
            for (int mt = 0; mt < 2; mt++){
                int rq = wq*32 + mt*16 + g;
                af[mt][0] = Qs[rq*68     + ks*8 + t4  ];
                af[mt][1] = Qs[(rq+8)*68 + ks*8 + t4  ];
                af[mt][2] = Qs[rq*68     + ks*8 + t4+4];
                af[mt][3] = Qs[(rq+8)*68 + ks*8 + t4+4];
            }
            #pragma unroll
            for (int nt = 0; nt < 4; nt++){
                int kn = wn*32 + nt*8 + g;
                bf[nt][0] = Ks[kn*68 + ks*8 + t4  ];
                bf[nt][1] = Ks[kn*68 + ks*8 + t4+4];
            }
            #pragma unroll
            for (int mt = 0; mt < 2; mt++)
                #pragma unroll
                for (int nt = 0; nt < 4; nt++)
                    mma8(acc1[mt][nt], af[mt], bf[nt]);
        }
        __syncthreads();           // Ks consumed
        if (j + 1 < PL/64){
            const unsigned* Kn = Kg + (long long)(j+1)*64*PHD;
            #pragma unroll
            for (int p = 0; p < 4; p++){
                int idx = tid + p*256; int r = idx >> 4, c = (idx & 15) << 2;
                CP16(smem_u32(&Ks[r*68 + c]), &Kn[(long long)r*PHD + c]);
            }
        } else {
            // stage K0 + V0 for phase 2
            #pragma unroll
            for (int p = 0; p < 4; p++){
                int idx = tid + p*256; int r = idx >> 4, c = (idx & 15) << 2;
                CP16(smem_u32(&Ks[r*68 + c]), &Kg[(long long)r*PHD + c]);
                CP16(smem_u32(&Vs[r*68 + c]), &Vg[(long long)r*PHD + c]);
            }
        }
        CP_COMMIT();
        #pragma unroll
        for (int mt = 0; mt < 2; mt++){
            const int qr = row0 + wq*32 + mt*16 + g;
            #pragma unroll
            for (int nt = 0; nt < 4; nt++){
                const int kc = j*64 + wn*32 + nt*8 + t4*2;
                float2 m0 = *(const float2*)&mask[(long long)qr*PL + kc];
                float2 m1 = *(const float2*)&mask[(long long)(qr+8)*PL + kc];
                rs[mt][0] += __expf(acc1[mt][nt][0]*scale*m0.x)
                           + __expf(acc1[mt][nt][1]*scale*m0.y);
                rs[mt][1] += __expf(acc1[mt][nt][2]*scale*m1.x)
                           + __expf(acc1[mt][nt][3]*scale*m1.y);
            }
        }
    }
    // reduce row sums: across t4 lanes (xor 1,2), then across wn warps (smem)
    #pragma unroll
    for (int mt = 0; mt < 2; mt++)
        #pragma unroll
        for (int hh = 0; hh < 2; hh++){
            rs[mt][hh] += __shfl_xor_sync(0xffffffffu, rs[mt][hh], 1);
            rs[mt][hh] += __shfl_xor_sync(0xffffffffu, rs[mt][hh], 2);
        }
    if (t4 == 0){
        #pragma unroll
        for (int mt = 0; mt < 2; mt++){
            const int lr = wq*32 + mt*16 + g;
            atomicAdd(&srs[lr],   rs[mt][0]);
            atomicAdd(&srs[lr+8], rs[mt][1]);
        }
    }
    __syncthreads();
    float inv[2][2];
    #pragma unroll
    for (int mt = 0; mt < 2; mt++){
        const int lr = wq*32 + mt*16 + g;
        inv[mt][0] = 1.f / srs[lr];
        inv[mt][1] = 1.f / srs[lr+8];
    }

    // ================= PHASE 2: attn write + ctx =================
    float acc[2][4][4] = {};
    for (int j = 0; j < PL/64; ++j){
        CP_WAIT0();
        __syncthreads();
        float acc1[2][4][4] = {};
        #pragma unroll
        for (int ks = 0; ks < 8; ks++){
            unsigned af[2][4], bf[4][2];
            #pragma unroll
            for (int mt = 0; mt < 2; mt++){
                int rq = wq*32 + mt*16 + g;
                af[mt][0] = Qs[rq*68     + ks*8 + t4  ];
                af[mt][1] = Qs[(rq+8)*68 + ks*8 + t4  ];
                af[mt][2] = Qs[rq*68     + ks*8 + t4+4];
                af[mt][3] = Qs[(rq+8)*68 + ks*8 + t4+4];
            }
            #pragma unroll
            for (int nt = 0; nt < 4; nt++){
                int kn = wn*32 + nt*8 + g;
                bf[nt][0] = Ks[kn*68 + ks*8 + t4  ];
                bf[nt][1] = Ks[kn*68 + ks*8 + t4+4];
            }
            #pragma unroll
            for (int mt = 0; mt < 2; mt++)
                #pragma unroll
                for (int nt = 0; nt < 4; nt++)
                    mma8(acc1[mt][nt], af[mt], bf[nt]);
        }
        __syncthreads();           // Ks consumed
        if (j + 1 < PL/64){
            const unsigned* Kn = Kg + (long long)(j+1)*64*PHD;
            #pragma unroll
            for (int p = 0; p < 4; p++){
                int idx = tid + p*256; int r = idx >> 4, c = (idx & 15) << 2;
                CP16(smem_u32(&Ks[r*68 + c]), &Kn[(long long)r*PHD + c]);
            }
            CP_COMMIT();
        }
        // normalized P: write attn to gmem + stage tf32 into Ps
        #pragma unroll
        for (int mt = 0; mt < 2; mt++){
            const int rq = wq*32 + mt*16 + g;
            const int qr = row0 + rq;
            #pragma unroll
            for (int nt = 0; nt < 4; nt++){
                const int cc = wn*32 + nt*8 + t4*2;
                const int kc = j*64 + cc;
                float2 m0 = *(const float2*)&mask[(long long)qr*PL + kc];
                float2 m1 = *(const float2*)&mask[(long long)(qr+8)*PL + kc];
                float p0 = __expf(acc1[mt][nt][0]*scale*m0.x)*inv[mt][0];
                float p1 = __expf(acc1[mt][nt][1]*scale*m0.y)*inv[mt][0];
                float p2 = __expf(acc1[mt][nt][2]*scale*m1.x)*inv[mt][1];
                float p3 = __expf(acc1[mt][nt][3]*scale*m1.y)*inv[mt][1];
                float2 o0 = {p0, p1}, o1 = {p2, p3};
                *(float2*)&attn[(long long)qr*PL + kc]     = o0;
                *(float2*)&attn[(long long)(qr+8)*PL + kc] = o1;
                uint2 u0 = {f2tf(p0), f2tf(p1)};
                uint2 u1 = {f2tf(p2), f2tf(p3)};
                *(uint2*)&Ps[rq*68 + cc]     = u0;
                *(uint2*)&Ps[(rq+8)*68 + cc] = u1;
            }
        }
        __syncthreads();           // Ps ready
        // ctx += P @ V
        #pragma unroll
        for (int ks = 0; ks < 8; ks++){
            unsigned af[2][4], bf[4][2];
            #pragma unroll
            for (int mt = 0; mt < 2; mt++){
                int rq = wq*32 + mt*16 + g;
                af[mt][0] = Ps[rq*68     + ks*8 + t4  ];
                af[mt][1] = Ps[(rq+8)*68 + ks*8 + t4  ];
                af[mt][2] = Ps[rq*68     + ks*8 + t4+4];
                af[mt][3] = Ps[(rq+8)*68 + ks*8 + t4+4];
            }
            #pragma unroll
            for (int nt = 0; nt < 4; nt++){
                int cn = wn*32 + nt*8 + g;
                bf[nt][0] = Vs[(ks*8 + t4  )*68 + cn];
                bf[nt][1] = Vs[(ks*8 + t4+4)*68 + cn];
            }
            #pragma unroll
            for (int mt = 0; mt < 2; mt++)
                #pragma unroll
                for (int nt = 0; nt < 4; nt++)
                    mma8(acc[mt][nt], af[mt], bf[nt]);
        }
        __syncthreads();           // Vs consumed
        if (j + 1 < PL/64){
            const unsigned* Vn = Vg + (long long)(j+1)*64*PHD;
            #pragma unroll
            for (int p = 0; p < 4; p++){
                int idx = tid + p*256; int r = idx >> 4, c = (idx & 15) << 2;
                CP16(smem_u32(&Vs[r*68 + c]), &Vn[(long long)r*PHD + c]);
            }
            CP_COMMIT();
        }
    }
    // epilogue: ctx (normalized) as tf32 bits, merged [B,L,D] layout
    const int bb = z >> 4, h = z & 15;
    #pragma unroll
    for (int mt = 0; mt < 2; mt++){
        #pragma unroll
        for (int nt = 0; nt < 4; nt++){
            const int lr = wq*32 + mt*16 + g;
            const int d = wn*32 + nt*8 + t4*2;
            {
                const int l = row0 + lr;
                int crow = bb*PL + h*128 + (l >> 4);
                int ccol = (l & 15)*64 + d;
                uint2 o = {f2tf(acc[mt][nt][0]), f2tf(acc[mt][nt][1])};
                *(uint2*)&ctx[(long long)crow*PD + ccol] = o;
            }
            {
                const int l = row0 + lr + 8;
                int crow = bb*PL + h*128 + (l >> 4);
                int ccol = (l & 15)*64 + d;
                uint2 o = {f2tf(acc[mt][nt][2]), f2tf(acc[mt][nt][3])};
                *(uint2*)&ctx[(long long)crow*PD + ccol] = o;
            }
        }
    }
}

// ---------------------------------------------------------------------------
extern "C" void kernel_launch(void* const* d_in, const int* in_sizes, int n_in,
                              void* d_out, int out_size)
{
    const float* x    = (const float*)d_in[0];
    const float* mask = (const float*)d_in[1];
    const float* Wqkv = (const float*)d_in[2];
    const float* bqkv = (const float*)d_in[3];
    const float* Wout = (const float*)d_in[4];
    const float* bout = (const float*)d_in[5];
    float* out = (float*)d_out;

    unsigned *xb, *wqkvb, *woutb, *q, *k, *v, *ctx;
    cudaGetSymbolAddress((void**)&xb,    g_xb);
    cudaGetSymbolAddress((void**)&wqkvb, g_wqkvb);
    cudaGetSymbolAddress((void**)&woutb, g_woutb);
    cudaGetSymbolAddress((void**)&q,     g_q);
    cudaGetSymbolAddress((void**)&k,     g_k);
    cudaGetSymbolAddress((void**)&v,     g_v);
    cudaGetSymbolAddress((void**)&ctx,   g_ctx);

    float* attn = out + OUT_ELEMS;   // attn lives in d_out after out

    // 0) pre-convert inputs to tf32 bits (one rna rounding, applied once)
    cvt_tf32_kernel<<<(PM*PD/4+255)/256, 256>>>((const float4*)x, (uint4*)xb, PM*PD/4);
    cvt_tf32_kernel<<<(PD*PN3/4+255)/256, 256>>>((const float4*)Wqkv, (uint4*)wqkvb, PD*PN3/4);
    cvt_tf32_kernel<<<(PD*PD/4+255)/256, 256>>>((const float4*)Wout, (uint4*)woutb, PD*PD/4);

    // 1) QKV projection + head split (tf32-bit output, no-transpose reshape)
    {
        dim3 grd(PN3/128, PM/128);
        gemm_tf32<1><<<grd, 256>>>(xb, wqkvb, bqkv, nullptr, PN3, PD, q, k, v);
    }
    // 2) two-phase flash: row sums, then attn write + ctx accumulate
    {
        const int smem_bytes = (8704 + 4352 + 4352 + 8704) * 4;  // 104448
        cudaFuncSetAttribute(flash2_attn,
                             cudaFuncAttributeMaxDynamicSharedMemorySize,
                             smem_bytes);
        dim3 gf(PL/128, PZH);
        flash2_attn<<<gf, 256, smem_bytes>>>(q, k, v, mask, attn, ctx);
    }
    // 3) output projection
    {
        dim3 grd(PD/128, PM/128);
        gemm_tf32<0><<<grd, 256>>>(ctx, woutb, bout, out, PD, PD,
                                   nullptr, nullptr, nullptr);
    }
}

// round 12
// speedup vs baseline: 1.3216x; 1.0228x over previous
#include <cuda_runtime.h>
#include <math.h>

// Problem constants
#define PB 2
#define PL 2048
#define PD 1024
#define PH 16
#define PHD 64
#define PM (PB*PL)          // 4096
#define PN3 (3*PD)          // 3072
#define PZH (PB*PH)         // 32
#define OUT_ELEMS (PB*PL*PD)                     // 4194304
#define ATTN_ELEMS ((long long)PZH*PL*PL)        // 134217728

// Scratch (allocation-free rule: device globals). tf32-bit buffers are unsigned.
__device__ unsigned g_xb[PM*PD];          // X as tf32 bits
__device__ unsigned g_wqkvb[PD*PN3];      // Wqkv as tf32 bits
__device__ unsigned g_woutb[PD*PD];       // Wout as tf32 bits
__device__ unsigned g_q[PZH*PL*PHD];      // q as tf32 bits
__device__ unsigned g_k[PZH*PL*PHD];
__device__ unsigned g_v[PZH*PL*PHD];
__device__ unsigned g_ctx[PM*PD];         // ctx as tf32 bits
__device__ float    g_inv[PZH*PL];        // per-row 1/sum

// ---------------------------------------------------------------------------
// helpers
// ---------------------------------------------------------------------------
__device__ __forceinline__ unsigned f2tf(float x){
    unsigned r; asm("cvt.rna.tf32.f32 %0, %1;" : "=r"(r) : "f"(x)); return r;
}
__device__ __forceinline__ void mma8(float* c, const unsigned* a, const unsigned* b){
    asm volatile("mma.sync.aligned.m16n8k8.row.col.f32.tf32.tf32.f32 "
        "{%0,%1,%2,%3}, {%4,%5,%6,%7}, {%8,%9}, {%0,%1,%2,%3};\n"
        : "+f"(c[0]),"+f"(c[1]),"+f"(c[2]),"+f"(c[3])
        : "r"(a[0]),"r"(a[1]),"r"(a[2]),"r"(a[3]), "r"(b[0]),"r"(b[1]));
}
__device__ __forceinline__ unsigned smem_u32(const void* p){
    return (unsigned)__cvta_generic_to_shared(p);
}
#define CP16(dst,src) asm volatile("cp.async.cg.shared.global [%0], [%1], 16;\n" :: "r"(dst), "l"(src))
#define CP_COMMIT()   asm volatile("cp.async.commit_group;\n")
#define CP_WAIT1()    asm volatile("cp.async.wait_group 1;\n")
#define CP_WAIT0()    asm volatile("cp.async.wait_group 0;\n")

// ---------------------------------------------------------------------------
// Elementwise fp32 -> tf32-bits conversion (vectorized)
// ---------------------------------------------------------------------------
__global__ void __launch_bounds__(256) cvt_tf32_kernel(
    const float4* __restrict__ in, uint4* __restrict__ out, int n4)
{
    int i = blockIdx.x * 256 + threadIdx.x;
    if (i < n4){
        float4 v = in[i];
        uint4 o = {f2tf(v.x), f2tf(v.y), f2tf(v.z), f2tf(v.w)};
        out[i] = o;
    }
}

// ---------------------------------------------------------------------------
// Normalize attn rows in place: attn[row][*] *= inv[row]. One warp per row.
// ---------------------------------------------------------------------------
__global__ void __launch_bounds__(256) norm_attn_kernel(
    float* __restrict__ attn, const float* __restrict__ inv)
{
    const int row  = blockIdx.x * 8 + (threadIdx.x >> 5);
    const int lane = threadIdx.x & 31;
    const float s = inv[row];
    float4* r = (float4*)(attn + (long long)row * PL);
    #pragma unroll
    for (int i = 0; i < 16; i++){
        float4 v = r[i*32 + lane];
        v.x *= s; v.y *= s; v.z *= s; v.w *= s;
        r[i*32 + lane] = v;
    }
}

// ---------------------------------------------------------------------------
// TF32 GEMM on pre-converted tf32-bit operands. 128x128 tile, BK=16,
// cp.async double buffer, 256 threads, 2 CTAs/SM.
// MODE 0: C(out float) = A@B + bias.
// MODE 1: QKV scatter into tf32-bit q/k/v (no-transpose reshape), +bias.
// ---------------------------------------------------------------------------
template<int MODE>
__global__ void __launch_bounds__(256, 2) gemm_tf32(
    const unsigned* __restrict__ A, const unsigned* __restrict__ B,
    const float* __restrict__ bias, float* __restrict__ C,
    int N, int K,
    unsigned* __restrict__ qd, unsigned* __restrict__ kd, unsigned* __restrict__ vd)
{
    __shared__ unsigned As[2][128][20];
    __shared__ unsigned Bs[2][16][136];
    const int tid = threadIdx.x, lane = tid & 31, warp = tid >> 5;
    const int wm = warp >> 2, wn = warp & 3;
    const int g = lane >> 2, t4 = lane & 3;
    const int row0 = blockIdx.y * 128, col0 = blockIdx.x * 128;
    float acc[4][4][4] = {};

    const int iters = K / 16;
    {
        #pragma unroll
        for (int p = 0; p < 2; p++){
            int idx = tid + p*256; int r = idx >> 2, kc = (idx & 3) << 2;
            CP16(smem_u32(&As[0][r][kc]), &A[(long long)(row0+r)*K + kc]);
        }
        #pragma unroll
        for (int p = 0; p < 2; p++){
            int idx = tid + p*256; int r = idx >> 5, c = (idx & 31) << 2;
            CP16(smem_u32(&Bs[0][r][c]), &B[(long long)r*N + col0 + c]);
        }
        CP_COMMIT();
    }
    for (int it = 0; it < iters; ++it){
        if (it + 1 < iters){
            const int k0 = (it+1)*16, nb = (it+1)&1;
            #pragma unroll
            for (int p = 0; p < 2; p++){
                int idx = tid + p*256; int r = idx >> 2, kc = (idx & 3) << 2;
                CP16(smem_u32(&As[nb][r][kc]), &A[(long long)(row0+r)*K + k0 + kc]);
            }
            #pragma unroll
            for (int p = 0; p < 2; p++){
                int idx = tid + p*256; int r = idx >> 5, c = (idx & 31) << 2;
                CP16(smem_u32(&Bs[nb][r][c]), &B[(long long)(k0+r)*N + col0 + c]);
            }
        }
        CP_COMMIT();
        CP_WAIT1();
        __syncthreads();
        const int b = it & 1;
        #pragma unroll
        for (int ks = 0; ks < 2; ks++){
            unsigned af[4][4], bf[4][2];
            #pragma unroll
            for (int mt = 0; mt < 4; mt++){
                int r = wm*64 + mt*16 + g;
                af[mt][0] = As[b][r  ][ks*8 + t4  ];
                af[mt][1] = As[b][r+8][ks*8 + t4  ];
                af[mt][2] = As[b][r  ][ks*8 + t4+4];
                af[mt][3] = As[b][r+8][ks*8 + t4+4];
            }
            #pragma unroll
            for (int nt = 0; nt < 4; nt++){
                int c = wn*32 + nt*8 + g;
                bf[nt][0] = Bs[b][ks*8 + t4  ][c];
                bf[nt][1] = Bs[b][ks*8 + t4+4][c];
            }
            #pragma unroll
            for (int mt = 0; mt < 4; mt++)
                #pragma unroll
                for (int nt = 0; nt < 4; nt++)
                    mma8(acc[mt][nt], af[mt], bf[nt]);
        }
        __syncthreads();
    }
    #pragma unroll
    for (int mt = 0; mt < 4; mt++){
        #pragma unroll
        for (int nt = 0; nt < 4; nt++){
            const int r = row0 + wm*64 + mt*16 + g;
            const int c = col0 + wn*32 + nt*8 + t4*2;
            float bx = bias ? bias[c] : 0.f, by = bias ? bias[c+1] : 0.f;
            float v0 = acc[mt][nt][0] + bx, v1 = acc[mt][nt][1] + by;
            float v2 = acc[mt][nt][2] + bx, v3 = acc[mt][nt][3] + by;
            if (MODE == 0){
                float2 o0 = {v0, v1}, o1 = {v2, v3};
                *(float2*)&C[(long long)r*N + c]     = o0;
                *(float2*)&C[(long long)(r+8)*N + c] = o1;
            } else {
                const int sel = c >> 10, cd = c & 1023;
                const int d = cd & 63, csl = cd >> 6;
                unsigned* dst = sel == 0 ? qd : (sel == 1 ? kd : vd);
                {
                    const int bb = r >> 11, lrow = r & 2047;
                    const int h = lrow >> 7, u = lrow & 127;
                    const int l2 = u*16 + csl;
                    long long off = ((long long)((bb*16 + h)*2048 + l2))*64 + d;
                    uint2 o = {f2tf(v0), f2tf(v1)}; *(uint2*)&dst[off] = o;
                }
                {
                    const int r2 = r + 8;
                    const int bb = r2 >> 11, lrow = r2 & 2047;
                    const int h = lrow >> 7, u = lrow & 127;
                    const int l2 = u*16 + csl;
                    long long off = ((long long)((bb*16 + h)*2048 + l2))*64 + d;
                    uint2 o = {f2tf(v2), f2tf(v3)}; *(uint2*)&dst[off] = o;
                }
            }
        }
    }
}

// ---------------------------------------------------------------------------
// SINGLE-PASS flash attention with attn materialization (unnormalized).
// Per j-iter: S = Q@K^T (mma) -> e = exp(scale*S*mask) -> write e to attn,
// accumulate row sums, stage e (tf32) -> ctx += P@V (mma).
// Epilogue: ctx *= 1/rowsum (exact by linearity), store 1/rowsum to g_inv.
// attn gets normalized later by norm_attn_kernel.
// Grid (PL/128, PZH), 256 threads, 2 CTAs/SM.
// smem: Qs[128][68] | Ks[64][68] | Vs[64][68] | Ps[128][68]
// ---------------------------------------------------------------------------
__global__ void __launch_bounds__(256, 2) flash1_attn(
    const unsigned* __restrict__ Qg, const unsigned* __restrict__ Kg,
    const unsigned* __restrict__ Vg, const float* __restrict__ mask,
    float* __restrict__ attn, unsigned* __restrict__ ctx,
    float* __restrict__ invg)
{
    extern __shared__ unsigned sm[];
    unsigned* Qs = sm;                         // 128*68
    unsigned* Ks = sm + 8704;                  // 64*68
    unsigned* Vs = sm + 13056;                 // 64*68
    unsigned* Ps = sm + 17408;                 // 128*68
    __shared__ float srs[128];

    const int z = blockIdx.y, row0 = blockIdx.x * 128;
    Qg += (long long)z * PL * PHD;
    Kg += (long long)z * PL * PHD;
    Vg += (long long)z * PL * PHD;
    attn += (long long)z * PL * PL;

    const int tid = threadIdx.x, lane = tid & 31, warp = tid >> 5;
    const int wq = warp >> 1, wn = warp & 1;   // 4 row-strips x 2 col-strips
    const int g = lane >> 2, t4 = lane & 3;
    const float scale = 0.03125f;

    // prologue: Q tile + first K and V tiles
    #pragma unroll
    for (int p = 0; p < 8; p++){
        int idx = tid + p*256; int r = idx >> 4, c = (idx & 15) << 2;
        CP16(smem_u32(&Qs[r*68 + c]), &Qg[(long long)(row0+r)*PHD + c]);
    }
    #pragma unroll
    for (int p = 0; p < 4; p++){
        int idx = tid + p*256; int r = idx >> 4, c = (idx & 15) << 2;
        CP16(smem_u32(&Ks[r*68 + c]), &Kg[(long long)r*PHD + c]);
        CP16(smem_u32(&Vs[r*68 + c]), &Vg[(long long)r*PHD + c]);
    }
    CP_COMMIT();
    if (tid < 128) srs[tid] = 0.f;

    float acc[2][4][4] = {};     // unnormalized ctx
    float rs[2][2] = {};         // running row sums

    for (int j = 0; j < PL/64; ++j){
        CP_WAIT0();
        __syncthreads();
        // ---- S = Q @ K^T ----
        float acc1[2][4][4] = {};
        #pragma unroll
        for (int ks = 0; ks < 8; ks++){
            unsigned af[2][4], bf[4][2];
            #pragma unroll
            for (int mt = 0; mt < 2; mt++){
                int rq = wq*32 + mt*16 + g;
                af[mt][0] = Qs[rq*68     + ks*8 + t4  ];
                af[mt][1] = Qs[(rq+8)*68 + ks*8 + t4  ];
                af[mt][2] = Qs[rq*68     + ks*8 + t4+4];
                af[mt][3] = Qs[(rq+8)*68 + ks*8 + t4+4];
            }
            #pragma unroll
            for (int nt = 0; nt < 4; nt++){
                int kn = wn*32 + nt*8 + g;
                bf[nt][0] = Ks[kn*68 + ks*8 + t4  ];
                bf[nt][1] = Ks[kn*68 + ks*8 + t4+4];
            }
            #pragma unroll
            for (int mt = 0; mt < 2; mt++)
                #pragma unroll
                for (int nt = 0; nt < 4; nt++)
                    mma8(acc1[mt][nt], af[mt], bf[nt]);
        }
        __syncthreads();           // Ks consumed
        if (j + 1 < PL/64){
            const unsigned* Kn = Kg + (long long)(j+1)*64*PHD;
            #pragma unroll
            for (int p = 0; p < 4; p++){
                int idx = tid + p*256; int r = idx >> 4, c = (idx & 15) << 2;
                CP16(smem_u32(&Ks[r*68 + c]), &Kn[(long long)r*PHD + c]);
            }
            CP_COMMIT();
        }
        // ---- e = exp(scale*S*mask): write attn (unnorm), row sums, stage P
        #pragma unroll
        for (int mt = 0; mt < 2; mt++){
            const int rq = wq*32 + mt*16 + g;
            const int qr = row0 + rq;
            #pragma unroll
            for (int nt = 0; nt < 4; nt++){
                const int cc = wn*32 + nt*8 + t4*2;
                const int kc = j*64 + cc;
                float2 m0 = *(const float2*)&mask[(long long)qr*PL + kc];
                float2 m1 = *(const float2*)&mask[(long long)(qr+8)*PL + kc];
                float e0 = __expf(acc1[mt][nt][0]*scale*m0.x);
                float e1 = __expf(acc1[mt][nt][1]*scale*m0.y);
                float e2 = __expf(acc1[mt][nt][2]*scale*m1.x);
                float e3 = __expf(acc1[mt][nt][3]*scale*m1.y);
                rs[mt][0] += e0 + e1;
                rs[mt][1] += e2 + e3;
                float2 o0 = {e0, e1}, o1 = {e2, e3};
                *(float2*)&attn[(long long)qr*PL + kc]     = o0;
                *(float2*)&attn[(long long)(qr+8)*PL + kc] = o1;
                uint2 u0 = {f2tf(e0), f2tf(e1)};
                uint2 u1 = {f2tf(e2), f2tf(e3)};
                *(uint2*)&Ps[rq*68 + cc]     = u0;
                *(uint2*)&Ps[(rq+8)*68 + cc] = u1;
            }
        }
        __syncthreads();           // Ps ready
        // ---- ctx += P @ V ----
        #pragma unroll
        for (int ks = 0; ks < 8; ks++){
            unsigned af[2][4], bf[4][2];
            #pragma unroll
            for (int mt = 0; mt < 2; mt++){
                int rq = wq*32 + mt*16 + g;
                af[mt][0] = Ps[rq*68     + ks*8 + t4  ];
                af[mt][1] = Ps[(rq+8)*68 + ks*8 + t4  ];
                af[mt][2] = Ps[rq*68     + ks*8 + t4+4];
                af[mt][3] = Ps[(rq+8)*68 + ks*8 + t4+4];
            }
            #pragma unroll
            for (int nt = 0; nt < 4; nt++){
                int cn = wn*32 + nt*8 + g;
                bf[nt][0] = Vs[(ks*8 + t4  )*68 + cn];
                bf[nt][1] = Vs[(ks*8 + t4+4)*68 + cn];
            }
            #pragma unroll
            for (int mt = 0; mt < 2; mt++)
                #pragma unroll
                for (int nt = 0; nt < 4; nt++)
                    mma8(acc[mt][nt], af[mt], bf[nt]);
        }
        __syncthreads();           // Vs consumed
        if (j + 1 < PL/64){
            const unsigned* Vn = Vg + (long long)(j+1)*64*PHD;
            #pragma unroll
            for (int p = 0; p < 4; p++){
                int idx = tid + p*256; int r = idx >> 4, c = (idx & 15) << 2;
                CP16(smem_u32(&Vs[r*68 + c]), &Vn[(long long)r*PHD + c]);
            }
            CP_COMMIT();
        }
    }
    // ---- reduce row sums: t4 lanes (xor 1,2), then wn warps via smem ----
    #pragma unroll
    for (int mt = 0; mt < 2; mt++)
        #pragma unroll
        for (int hh = 0; hh < 2; hh++){
            rs[mt][hh] += __shfl_xor_sync(0xffffffffu, rs[mt][hh], 1);
            rs[mt][hh] += __shfl_xor_sync(0xffffffffu, rs[mt][hh], 2);
        }
    if (t4 == 0){
        #pragma unroll
        for (int mt = 0; mt < 2; mt++){
            const int lr = wq*32 + mt*16 + g;
            atomicAdd(&srs[lr],   rs[mt][0]);
            atomicAdd(&srs[lr+8], rs[mt][1]);
        }
    }
    __syncthreads();
    // store 1/rowsum for the attn-normalize pass
    if (tid < 128) invg[z*PL + row0 + tid] = 1.f / srs[tid];
    // ---- epilogue: ctx * inv as tf32 bits, merged [B,L,D] layout ----
    const int bb = z >> 4, h = z & 15;
    #pragma unroll
    for (int mt = 0; mt < 2; mt++){
        const int lr = wq*32 + mt*16 + g;
        const float inv0 = 1.f / srs[lr];
        const float inv1 = 1.f / srs[lr+8];
        #pragma unroll
        for (int nt = 0; nt < 4; nt++){
            const int d = wn*32 + nt*8 + t4*2;
            {
                const int l = row0 + lr;
                int crow = bb*PL + h*128 + (l >> 4);
                int ccol = (l & 15)*64 + d;
                uint2 o = {f2tf(acc[mt][nt][0]*inv0), f2tf(acc[mt][nt][1]*inv0)};
                *(uint2*)&ctx[(long long)crow*PD + ccol] = o;
            }
            {
                const int l = row0 + lr + 8;
                int crow = bb*PL + h*128 + (l >> 4);
                int ccol = (l & 15)*64 + d;
                uint2 o = {f2tf(acc[mt][nt][2]*inv1), f2tf(acc[mt][nt][3]*inv1)};
                *(uint2*)&ctx[(long long)crow*PD + ccol] = o;
            }
        }
    }
}

// ---------------------------------------------------------------------------
extern "C" void kernel_launch(void* const* d_in, const int* in_sizes, int n_in,
                              void* d_out, int out_size)
{
    const float* x    = (const float*)d_in[0];
    const float* mask = (const float*)d_in[1];
    const float* Wqkv = (const float*)d_in[2];
    const float* bqkv = (const float*)d_in[3];
    const float* Wout = (const float*)d_in[4];
    const float* bout = (const float*)d_in[5];
    float* out = (float*)d_out;

    unsigned *xb, *wqkvb, *woutb, *q, *k, *v, *ctx; float* invg;
    cudaGetSymbolAddress((void**)&xb,    g_xb);
    cudaGetSymbolAddress((void**)&wqkvb, g_wqkvb);
    cudaGetSymbolAddress((void**)&woutb, g_woutb);
    cudaGetSymbolAddress((void**)&q,     g_q);
    cudaGetSymbolAddress((void**)&k,     g_k);
    cudaGetSymbolAddress((void**)&v,     g_v);
    cudaGetSymbolAddress((void**)&ctx,   g_ctx);
    cudaGetSymbolAddress((void**)&invg,  g_inv);

    float* attn = out + OUT_ELEMS;   // attn lives in d_out after out

    // 0) pre-convert inputs to tf32 bits
    cvt_tf32_kernel<<<(PM*PD/4+255)/256, 256>>>((const float4*)x, (uint4*)xb, PM*PD/4);
    cvt_tf32_kernel<<<(PD*PN3/4+255)/256, 256>>>((const float4*)Wqkv, (uint4*)wqkvb, PD*PN3/4);
    cvt_tf32_kernel<<<(PD*PD/4+255)/256, 256>>>((const float4*)Wout, (uint4*)woutb, PD*PD/4);

    // 1) QKV projection + head split
    {
        dim3 grd(PN3/128, PM/128);
        gemm_tf32<1><<<grd, 256>>>(xb, wqkvb, bqkv, nullptr, PN3, PD, q, k, v);
    }
    // 2) single-pass flash: unnormalized attn + ctx + row sums
    {
        const int smem_bytes = (8704 + 4352 + 4352 + 8704) * 4;  // 104448
        cudaFuncSetAttribute(flash1_attn,
                             cudaFuncAttributeMaxDynamicSharedMemorySize,
                             smem_bytes);
        dim3 gf(PL/128, PZH);
        flash1_attn<<<gf, 256, smem_bytes>>>(q, k, v, mask, attn, ctx, invg);
    }
    // 3) output projection (depends only on ctx)
    {
        dim3 grd(PD/128, PM/128);
        gemm_tf32<0><<<grd, 256>>>(ctx, woutb, bout, out, PD, PD,
                                   nullptr, nullptr, nullptr);
    }
    // 4) normalize attn rows in place (pure bandwidth)
    norm_attn_kernel<<<PZH*PL/8, 256>>>(attn, invg);
}

// round 13
// speedup vs baseline: 1.8336x; 1.3874x over previous
#include <cuda_runtime.h>
#include <cuda_fp16.h>
#include <math.h>

// Problem constants
#define PB 2
#define PL 2048
#define PD 1024
#define PH 16
#define PHD 64
#define PM (PB*PL)          // 4096
#define PN3 (3*PD)          // 3072
#define PZH (PB*PH)         // 32
#define OUT_ELEMS (PB*PL*PD)                     // 4194304
#define ATTN_ELEMS ((long long)PZH*PL*PL)        // 134217728

// Scratch (allocation-free rule: device globals), fp16 operands.
__device__ __align__(256) __half g_xh[PM*PD];        // X fp16 [4096][1024]
__device__ __align__(256) __half g_wqkvt[PN3*PD];    // Wqkv^T fp16 [3072][1024]
__device__ __align__(256) __half g_woutt[PD*PD];     // Wout^T fp16 [1024][1024]
__device__ __align__(256) __half g_q[PZH*PL*PHD];    // q fp16 [z][l][d]
__device__ __align__(256) __half g_k[PZH*PL*PHD];    // k fp16 [z][l][d]
__device__ __align__(256) __half g_vt[PZH*PHD*PL];   // v fp16 TRANSPOSED [z][d][l]
__device__ __align__(256) __half g_ctx[PM*PD];       // ctx fp16 [4096][1024]
__device__ float g_inv[PZH*PL];                      // per-row 1/sum

// ---------------------------------------------------------------------------
// helpers
// ---------------------------------------------------------------------------
__device__ __forceinline__ void mma16(float* c, const unsigned* a, const unsigned* b){
    asm volatile("mma.sync.aligned.m16n8k16.row.col.f32.f16.f16.f32 "
        "{%0,%1,%2,%3}, {%4,%5,%6,%7}, {%8,%9}, {%0,%1,%2,%3};\n"
        : "+f"(c[0]),"+f"(c[1]),"+f"(c[2]),"+f"(c[3])
        : "r"(a[0]),"r"(a[1]),"r"(a[2]),"r"(a[3]), "r"(b[0]),"r"(b[1]));
}
__device__ __forceinline__ unsigned smem_u32(const void* p){
    return (unsigned)__cvta_generic_to_shared(p);
}
__device__ __forceinline__ unsigned h2u(__half2 h){ return *(unsigned*)&h; }
#define CP16(dst,src) asm volatile("cp.async.cg.shared.global [%0], [%1], 16;\n" :: "r"(dst), "l"(src))
#define CP_COMMIT()   asm volatile("cp.async.commit_group;\n")
#define CP_WAIT1()    asm volatile("cp.async.wait_group 1;\n")
#define CP_WAIT0()    asm volatile("cp.async.wait_group 0;\n")

// ---------------------------------------------------------------------------
// fp32 -> fp16 elementwise (vectorized)
// ---------------------------------------------------------------------------
__global__ void __launch_bounds__(256) cvt_fp16_kernel(
    const float4* __restrict__ in, uint2* __restrict__ out, int n4)
{
    int i = blockIdx.x * 256 + threadIdx.x;
    if (i < n4){
        float4 v = in[i];
        uint2 o = {h2u(__floats2half2_rn(v.x, v.y)),
                   h2u(__floats2half2_rn(v.z, v.w))};
        out[i] = o;
    }
}

// ---------------------------------------------------------------------------
// fp32 [K][N] -> fp16 transposed [N][K]  (tiled, smem)
// ---------------------------------------------------------------------------
__global__ void __launch_bounds__(256) cvt_transpose_kernel(
    const float* __restrict__ W, __half* __restrict__ Wt, int K, int N)
{
    __shared__ float tile[32][33];
    const int k0 = blockIdx.y * 32, n0 = blockIdx.x * 32;
    const int tx = threadIdx.x & 31, ty = threadIdx.x >> 5;  // 32x8
    #pragma unroll
    for (int i = 0; i < 32; i += 8)
        tile[ty+i][tx] = W[(long long)(k0+ty+i)*N + n0 + tx];
    __syncthreads();
    #pragma unroll
    for (int i = 0; i < 32; i += 8)
        Wt[(long long)(n0+ty+i)*K + k0 + tx] = __float2half(tile[tx][ty+i]);
}

// ---------------------------------------------------------------------------
// Normalize attn rows in place: attn[row][*] *= inv[row]. One warp per row.
// ---------------------------------------------------------------------------
__global__ void __launch_bounds__(256) norm_attn_kernel(
    float* __restrict__ attn, const float* __restrict__ inv)
{
    const int row  = blockIdx.x * 8 + (threadIdx.x >> 5);
    const int lane = threadIdx.x & 31;
    const float s = inv[row];
    float4* r = (float4*)(attn + (long long)row * PL);
    #pragma unroll
    for (int i = 0; i < 16; i++){
        float4 v = r[i*32 + lane];
        v.x *= s; v.y *= s; v.z *= s; v.w *= s;
        r[i*32 + lane] = v;
    }
}

// ---------------------------------------------------------------------------
// FP16 GEMM: C[M][N] = A[M][K] @ Bt[N][K]^T (+bias). 128x128 tile, BK=32,
// cp.async double buffer, 256 threads, 2 CTAs/SM. All fragment loads are
// contiguous half2 (B pre-transposed), bank-conflict-free pads.
// MODE 0: C float out. MODE 1: QKV scatter (q/k row-major, v transposed).
// ---------------------------------------------------------------------------
template<int MODE>
__global__ void __launch_bounds__(256, 2) gemm_fp16(
    const __half* __restrict__ A, const __half* __restrict__ Bt,
    const float* __restrict__ bias, float* __restrict__ C,
    int N, int K,
    __half* __restrict__ qd, __half* __restrict__ kd, __half* __restrict__ vd)
{
    __shared__ __half As[2][128][40];   // row stride 80B (5x16)
    __shared__ __half Bs[2][128][40];
    const int tid = threadIdx.x, lane = tid & 31, warp = tid >> 5;
    const int wm = warp >> 2, wn = warp & 3;          // 2 x 4 warps
    const int g = lane >> 2, t4 = lane & 3;
    const int row0 = blockIdx.y * 128, col0 = blockIdx.x * 128;
    float acc[4][4][4] = {};

    const int iters = K / 32;
    // prologue
    #pragma unroll
    for (int p = 0; p < 2; p++){
        int idx = tid + p*256; int r = idx >> 2, ch = (idx & 3) << 3;
        CP16(smem_u32(&As[0][r][ch]), &A[(long long)(row0+r)*K + ch]);
        CP16(smem_u32(&Bs[0][r][ch]), &Bt[(long long)(col0+r)*K + ch]);
    }
    CP_COMMIT();
    for (int it = 0; it < iters; ++it){
        if (it + 1 < iters){
            const int k0 = (it+1)*32, nb = (it+1)&1;
            #pragma unroll
            for (int p = 0; p < 2; p++){
                int idx = tid + p*256; int r = idx >> 2, ch = (idx & 3) << 3;
                CP16(smem_u32(&As[nb][r][ch]), &A[(long long)(row0+r)*K + k0 + ch]);
                CP16(smem_u32(&Bs[nb][r][ch]), &Bt[(long long)(col0+r)*K + k0 + ch]);
            }
        }
        CP_COMMIT();
        CP_WAIT1();
        __syncthreads();
        const int b = it & 1;
        #pragma unroll
        for (int ks = 0; ks < 2; ks++){
            unsigned af[4][4], bf[4][2];
            #pragma unroll
            for (int mt = 0; mt < 4; mt++){
                int r = wm*64 + mt*16 + g;
                af[mt][0] = *(unsigned*)&As[b][r  ][ks*16 + t4*2    ];
                af[mt][1] = *(unsigned*)&As[b][r+8][ks*16 + t4*2    ];
                af[mt][2] = *(unsigned*)&As[b][r  ][ks*16 + t4*2 + 8];
                af[mt][3] = *(unsigned*)&As[b][r+8][ks*16 + t4*2 + 8];
            }
            #pragma unroll
            for (int nt = 0; nt < 4; nt++){
                int c = wn*32 + nt*8 + g;
                bf[nt][0] = *(unsigned*)&Bs[b][c][ks*16 + t4*2    ];
                bf[nt][1] = *(unsigned*)&Bs[b][c][ks*16 + t4*2 + 8];
            }
            #pragma unroll
            for (int mt = 0; mt < 4; mt++)
                #pragma unroll
                for (int nt = 0; nt < 4; nt++)
                    mma16(acc[mt][nt], af[mt], bf[nt]);
        }
        __syncthreads();
    }
    // epilogue
    #pragma unroll
    for (int mt = 0; mt < 4; mt++){
        #pragma unroll
        for (int nt = 0; nt < 4; nt++){
            const int r = row0 + wm*64 + mt*16 + g;
            const int c = col0 + wn*32 + nt*8 + t4*2;
            float bx = bias ? bias[c] : 0.f, by = bias ? bias[c+1] : 0.f;
            float v0 = acc[mt][nt][0] + bx, v1 = acc[mt][nt][1] + by;
            float v2 = acc[mt][nt][2] + bx, v3 = acc[mt][nt][3] + by;
            if (MODE == 0){
                float2 o0 = {v0, v1}, o1 = {v2, v3};
                *(float2*)&C[(long long)r*N + c]     = o0;
                *(float2*)&C[(long long)(r+8)*N + c] = o1;
            } else {
                // no-transpose reshape: h from seq block, l2 mixes seq+chan
                const int sel = c >> 10, cd = c & 1023;
                const int d = cd & 63, csl = cd >> 6;
                #pragma unroll
                for (int hh = 0; hh < 2; hh++){
                    const int rr = r + hh*8;
                    const float a0 = hh ? v2 : v0, a1 = hh ? v3 : v1;
                    const int bb = rr >> 11, lrow = rr & 2047;
                    const int z = bb*16 + (lrow >> 7);
                    const int l2 = (lrow & 127)*16 + csl;
                    if (sel == 2){
                        // v transposed: [z][d][l]
                        vd[((long long)z*PHD + d    )*PL + l2] = __float2half(a0);
                        vd[((long long)z*PHD + d + 1)*PL + l2] = __float2half(a1);
                    } else {
                        __half* dst = sel == 0 ? qd : kd;
                        long long off = ((long long)z*PL + l2)*PHD + d;
                        *(unsigned*)&dst[off] = h2u(__floats2half2_rn(a0, a1));
                    }
                }
            }
        }
    }
}

// ---------------------------------------------------------------------------
// SINGLE-PASS fp16 flash attention with unnormalized attn materialization.
// Per 64-kv-row iter: S = Q@K^T -> e = exp(scale*S*mask) -> write e to attn,
// row sums, stage e fp16 -> ctx += P@V. Epilogue: ctx *= 1/rowsum, fp16 out.
// Grid (PL/128, PZH), 256 threads, 2 CTAs/SM.
// smem (halves): Qs[128][72] | Ks[64][72] | Vs[64][72] | Ps[128][72]
// ---------------------------------------------------------------------------
__global__ void __launch_bounds__(256, 2) flash1_attn(
    const __half* __restrict__ Qg, const __half* __restrict__ Kg,
    const __half* __restrict__ Vtg, const float* __restrict__ mask,
    float* __restrict__ attn, __half* __restrict__ ctx,
    float* __restrict__ invg)
{
    extern __shared__ __half smh[];
    __half* Qs = smh;                 // 128*72 = 9216
    __half* Ks = smh + 9216;          // 64*72  = 4608
    __half* Vs = smh + 13824;         // 64*72
    __half* Ps = smh + 18432;         // 128*72
    __shared__ float srs[128];

    const int z = blockIdx.y, row0 = blockIdx.x * 128;
    Qg  += (long long)z * PL * PHD;
    Kg  += (long long)z * PL * PHD;
    Vtg += (long long)z * PHD * PL;   // [d][l]
    attn += (long long)z * PL * PL;

    const int tid = threadIdx.x, lane = tid & 31, warp = tid >> 5;
    const int wq = warp >> 1, wn = warp & 1;   // 4 row-strips x 2 col-strips
    const int g = lane >> 2, t4 = lane & 3;
    const float scale = 0.03125f;

    // prologue: Q tile (128x64) + first K tile (64x64) + first V tile (64hd x 64kv)
    #pragma unroll
    for (int p = 0; p < 4; p++){
        int idx = tid + p*256; int r = idx >> 3, ch = (idx & 7) << 3;
        CP16(smem_u32(&Qs[r*72 + ch]), &Qg[(long long)(row0+r)*PHD + ch]);
    }
    #pragma unroll
    for (int p = 0; p < 2; p++){
        int idx = tid + p*256; int r = idx >> 3, ch = (idx & 7) << 3;
        CP16(smem_u32(&Ks[r*72 + ch]), &Kg[(long long)r*PHD + ch]);
        CP16(smem_u32(&Vs[r*72 + ch]), &Vtg[(long long)r*PL + ch]);
    }
    CP_COMMIT();
    if (tid < 128) srs[tid] = 0.f;

    float acc[2][4][4] = {};     // unnormalized ctx
    float rs[2][2] = {};         // running row sums

    for (int j = 0; j < PL/64; ++j){
        CP_WAIT0();
        __syncthreads();
        // ---- S = Q @ K^T (4 k-steps of 16) ----
        float acc1[2][4][4] = {};
        #pragma unroll
        for (int ks = 0; ks < 4; ks++){
            unsigned af[2][4], bf[4][2];
            #pragma unroll
            for (int mt = 0; mt < 2; mt++){
                int rq = wq*32 + mt*16 + g;
                af[mt][0] = *(unsigned*)&Qs[rq*72     + ks*16 + t4*2    ];
                af[mt][1] = *(unsigned*)&Qs[(rq+8)*72 + ks*16 + t4*2    ];
                af[mt][2] = *(unsigned*)&Qs[rq*72     + ks*16 + t4*2 + 8];
                af[mt][3] = *(unsigned*)&Qs[(rq+8)*72 + ks*16 + t4*2 + 8];
            }
            #pragma unroll
            for (int nt = 0; nt < 4; nt++){
                int kn = wn*32 + nt*8 + g;
                bf[nt][0] = *(unsigned*)&Ks[kn*72 + ks*16 + t4*2    ];
                bf[nt][1] = *(unsigned*)&Ks[kn*72 + ks*16 + t4*2 + 8];
            }
            #pragma unroll
            for (int mt = 0; mt < 2; mt++)
                #pragma unroll
                for (int nt = 0; nt < 4; nt++)
                    mma16(acc1[mt][nt], af[mt], bf[nt]);
        }
        __syncthreads();           // Ks consumed
        if (j + 1 < PL/64){
            const __half* Kn = Kg + (long long)(j+1)*64*PHD;
            #pragma unroll
            for (int p = 0; p < 2; p++){
                int idx = tid + p*256; int r = idx >> 3, ch = (idx & 7) << 3;
                CP16(smem_u32(&Ks[r*72 + ch]), &Kn[(long long)r*PHD + ch]);
            }
            CP_COMMIT();
        }
        // ---- e = exp(scale*S*mask): attn write (unnorm), row sums, stage P
        #pragma unroll
        for (int mt = 0; mt < 2; mt++){
            const int rq = wq*32 + mt*16 + g;
            const int qr = row0 + rq;
            #pragma unroll
            for (int nt = 0; nt < 4; nt++){
                const int cc = wn*32 + nt*8 + t4*2;
                const int kc = j*64 + cc;
                float2 m0 = *(const float2*)&mask[(long long)qr*PL + kc];
                float2 m1 = *(const float2*)&mask[(long long)(qr+8)*PL + kc];
                float e0 = __expf(acc1[mt][nt][0]*scale*m0.x);
                float e1 = __expf(acc1[mt][nt][1]*scale*m0.y);
                float e2 = __expf(acc1[mt][nt][2]*scale*m1.x);
                float e3 = __expf(acc1[mt][nt][3]*scale*m1.y);
                rs[mt][0] += e0 + e1;
                rs[mt][1] += e2 + e3;
                float2 o0 = {e0, e1}, o1 = {e2, e3};
                *(float2*)&attn[(long long)qr*PL + kc]     = o0;
                *(float2*)&attn[(long long)(qr+8)*PL + kc] = o1;
                *(unsigned*)&Ps[rq*72 + cc]     = h2u(__floats2half2_rn(e0, e1));
                *(unsigned*)&Ps[(rq+8)*72 + cc] = h2u(__floats2half2_rn(e2, e3));
            }
        }
        __syncthreads();           // Ps ready
        // ---- ctx += P @ V (4 k-steps over 64 kv) ----
        #pragma unroll
        for (int ks = 0; ks < 4; ks++){
            unsigned af[2][4], bf[4][2];
            #pragma unroll
            for (int mt = 0; mt < 2; mt++){
                int rq = wq*32 + mt*16 + g;
                af[mt][0] = *(unsigned*)&Ps[rq*72     + ks*16 + t4*2    ];
                af[mt][1] = *(unsigned*)&Ps[(rq+8)*72 + ks*16 + t4*2    ];
                af[mt][2] = *(unsigned*)&Ps[rq*72     + ks*16 + t4*2 + 8];
                af[mt][3] = *(unsigned*)&Ps[(rq+8)*72 + ks*16 + t4*2 + 8];
            }
            #pragma unroll
            for (int nt = 0; nt < 4; nt++){
                int cn = wn*32 + nt*8 + g;        // hd column = Vs row
                bf[nt][0] = *(unsigned*)&Vs[cn*72 + ks*16 + t4*2    ];
                bf[nt][1] = *(unsigned*)&Vs[cn*72 + ks*16 + t4*2 + 8];
            }
            #pragma unroll
            for (int mt = 0; mt < 2; mt++)
                #pragma unroll
                for (int nt = 0; nt < 4; nt++)
                    mma16(acc[mt][nt], af[mt], bf[nt]);
        }
        __syncthreads();           // Vs consumed
        if (j + 1 < PL/64){
            const __half* Vn = Vtg + (long long)(j+1)*64;   // next 64 kv cols
            #pragma unroll
            for (int p = 0; p < 2; p++){
                int idx = tid + p*256; int r = idx >> 3, ch = (idx & 7) << 3;
                CP16(smem_u32(&Vs[r*72 + ch]), &Vn[(long long)r*PL + ch]);
            }
            CP_COMMIT();
        }
    }
    // ---- reduce row sums: t4 lanes (xor 1,2), then wn warps via smem ----
    #pragma unroll
    for (int mt = 0; mt < 2; mt++)
        #pragma unroll
        for (int hh = 0; hh < 2; hh++){
            rs[mt][hh] += __shfl_xor_sync(0xffffffffu, rs[mt][hh], 1);
            rs[mt][hh] += __shfl_xor_sync(0xffffffffu, rs[mt][hh], 2);
        }
    if (t4 == 0){
        #pragma unroll
        for (int mt = 0; mt < 2; mt++){
            const int lr = wq*32 + mt*16 + g;
            atomicAdd(&srs[lr],   rs[mt][0]);
            atomicAdd(&srs[lr+8], rs[mt][1]);
        }
    }
    __syncthreads();
    if (tid < 128) invg[z*PL + row0 + tid] = 1.f / srs[tid];
    // ---- epilogue: ctx*inv as fp16, merged [B,L,D] layout ----
    const int bb = z >> 4, h = z & 15;
    #pragma unroll
    for (int mt = 0; mt < 2; mt++){
        const int lr = wq*32 + mt*16 + g;
        const float inv0 = 1.f / srs[lr];
        const float inv1 = 1.f / srs[lr+8];
        #pragma unroll
        for (int nt = 0; nt < 4; nt++){
            const int d = wn*32 + nt*8 + t4*2;
            {
                const int l = row0 + lr;
                int crow = bb*PL + h*128 + (l >> 4);
                int ccol = (l & 15)*64 + d;
                *(unsigned*)&ctx[(long long)crow*PD + ccol] =
                    h2u(__floats2half2_rn(acc[mt][nt][0]*inv0, acc[mt][nt][1]*inv0));
            }
            {
                const int l = row0 + lr + 8;
                int crow = bb*PL + h*128 + (l >> 4);
                int ccol = (l & 15)*64 + d;
                *(unsigned*)&ctx[(long long)crow*PD + ccol] =
                    h2u(__floats2half2_rn(acc[mt][nt][2]*inv1, acc[mt][nt][3]*inv1));
            }
        }
    }
}

// ---------------------------------------------------------------------------
extern "C" void kernel_launch(void* const* d_in, const int* in_sizes, int n_in,
                              void* d_out, int out_size)
{
    const float* x    = (const float*)d_in[0];
    const float* mask = (const float*)d_in[1];
    const float* Wqkv = (const float*)d_in[2];
    const float* bqkv = (const float*)d_in[3];
    const float* Wout = (const float*)d_in[4];
    const float* bout = (const float*)d_in[5];
    float* out = (float*)d_out;

    __half *xh, *wqkvt, *woutt, *q, *k, *vt, *ctx; float* invg;
    cudaGetSymbolAddress((void**)&xh,    g_xh);
    cudaGetSymbolAddress((void**)&wqkvt, g_wqkvt);
    cudaGetSymbolAddress((void**)&woutt, g_woutt);
    cudaGetSymbolAddress((void**)&q,     g_q);
    cudaGetSymbolAddress((void**)&k,     g_k);
    cudaGetSymbolAddress((void**)&vt,    g_vt);
    cudaGetSymbolAddress((void**)&ctx,   g_ctx);
    cudaGetSymbolAddress((void**)&invg,  g_inv);

    float* attn = out + OUT_ELEMS;   // attn lives in d_out after out

    // 0) convert inputs to fp16 (weights transposed to [N][K])
    cvt_fp16_kernel<<<(PM*PD/4+255)/256, 256>>>((const float4*)x, (uint2*)xh, PM*PD/4);
    {
        dim3 gt(PN3/32, PD/32);
        cvt_transpose_kernel<<<gt, 256>>>(Wqkv, wqkvt, PD, PN3);
    }
    {
        dim3 gt(PD/32, PD/32);
        cvt_transpose_kernel<<<gt, 256>>>(Wout, woutt, PD, PD);
    }

    // 1) QKV projection + head split (q/k row-major, v transposed per head)
    {
        dim3 grd(PN3/128, PM/128);
        gemm_fp16<1><<<grd, 256>>>(xh, wqkvt, bqkv, nullptr, PN3, PD,
                                   q, k, vt);
    }
    // 2) single-pass flash: unnormalized attn + ctx + row sums
    {
        const int smem_bytes = 27648 * 2;   // 55296 B
        cudaFuncSetAttribute(flash1_attn,
                             cudaFuncAttributeMaxDynamicSharedMemorySize,
                             smem_bytes);
        dim3 gf(PL/128, PZH);
        flash1_attn<<<gf, 256, smem_bytes>>>(q, k, vt, mask, attn, ctx, invg);
    }
    // 3) output projection
    {
        dim3 grd(PD/128, PM/128);
        gemm_fp16<0><<<grd, 256>>>(ctx, woutt, bout, out, PD, PD,
                                   nullptr, nullptr, nullptr);
    }
    // 4) normalize attn rows in place (pure bandwidth)
    norm_attn_kernel<<<PZH*PL/8, 256>>>(attn, invg);
}

// round 14
// speedup vs baseline: 1.9917x; 1.0862x over previous
#include <cuda_runtime.h>
#include <cuda_fp16.h>
#include <math.h>

// Problem constants
#define PB 2
#define PL 2048
#define PD 1024
#define PH 16
#define PHD 64
#define PM (PB*PL)          // 4096
#define PN3 (3*PD)          // 3072
#define PZH (PB*PH)         // 32
#define OUT_ELEMS (PB*PL*PD)                     // 4194304
#define ATTN_ELEMS ((long long)PZH*PL*PL)        // 134217728

// Scratch (allocation-free rule: device globals), fp16 operands.
__device__ __align__(256) __half g_xh[PM*PD];        // X fp16 [4096][1024]
__device__ __align__(256) __half g_wqkvt[PN3*PD];    // Wqkv^T fp16 [3072][1024]
__device__ __align__(256) __half g_woutt[PD*PD];     // Wout^T fp16 [1024][1024]
__device__ __align__(256) __half g_q[PZH*PL*PHD];    // q fp16 [z][l][d]
__device__ __align__(256) __half g_k[PZH*PL*PHD];    // k fp16 [z][l][d]
__device__ __align__(256) __half g_vt[PZH*PHD*PL];   // v fp16 TRANSPOSED [z][d][l]
__device__ __align__(256) __half g_ctx[PM*PD];       // ctx fp16 [4096][1024]
__device__ __align__(256) __half g_eh[134217728];    // unnormalized exp, fp16 (268MB)
__device__ float g_inv[PZH*PL];                      // per-row 1/sum

// ---------------------------------------------------------------------------
// helpers
// ---------------------------------------------------------------------------
__device__ __forceinline__ void mma16(float* c, const unsigned* a, const unsigned* b){
    asm volatile("mma.sync.aligned.m16n8k16.row.col.f32.f16.f16.f32 "
        "{%0,%1,%2,%3}, {%4,%5,%6,%7}, {%8,%9}, {%0,%1,%2,%3};\n"
        : "+f"(c[0]),"+f"(c[1]),"+f"(c[2]),"+f"(c[3])
        : "r"(a[0]),"r"(a[1]),"r"(a[2]),"r"(a[3]), "r"(b[0]),"r"(b[1]));
}
__device__ __forceinline__ unsigned smem_u32(const void* p){
    return (unsigned)__cvta_generic_to_shared(p);
}
__device__ __forceinline__ unsigned h2u(__half2 h){ return *(unsigned*)&h; }
#define CP16(dst,src) asm volatile("cp.async.cg.shared.global [%0], [%1], 16;\n" :: "r"(dst), "l"(src))
#define CP_COMMIT()   asm volatile("cp.async.commit_group;\n")
#define CP_WAIT1()    asm volatile("cp.async.wait_group 1;\n")
#define CP_WAIT0()    asm volatile("cp.async.wait_group 0;\n")

// ---------------------------------------------------------------------------
// fp32 -> fp16 elementwise (vectorized)
// ---------------------------------------------------------------------------
__global__ void __launch_bounds__(256) cvt_fp16_kernel(
    const float4* __restrict__ in, uint2* __restrict__ out, int n4)
{
    int i = blockIdx.x * 256 + threadIdx.x;
    if (i < n4){
        float4 v = in[i];
        uint2 o = {h2u(__floats2half2_rn(v.x, v.y)),
                   h2u(__floats2half2_rn(v.z, v.w))};
        out[i] = o;
    }
}

// ---------------------------------------------------------------------------
// fp32 [K][N] -> fp16 transposed [N][K]  (tiled, smem)
// ---------------------------------------------------------------------------
__global__ void __launch_bounds__(256) cvt_transpose_kernel(
    const float* __restrict__ W, __half* __restrict__ Wt, int K, int N)
{
    __shared__ float tile[32][33];
    const int k0 = blockIdx.y * 32, n0 = blockIdx.x * 32;
    const int tx = threadIdx.x & 31, ty = threadIdx.x >> 5;  // 32x8
    #pragma unroll
    for (int i = 0; i < 32; i += 8)
        tile[ty+i][tx] = W[(long long)(k0+ty+i)*N + n0 + tx];
    __syncthreads();
    #pragma unroll
    for (int i = 0; i < 32; i += 8)
        Wt[(long long)(n0+ty+i)*K + k0 + tx] = __float2half(tile[tx][ty+i]);
}

// ---------------------------------------------------------------------------
// Expand-normalize: attn_f32[row][*] = eh_f16[row][*] * inv[row].
// One warp per row; fp16 in (268MB), fp32 out (536MB).
// ---------------------------------------------------------------------------
__global__ void __launch_bounds__(256) norm_attn_kernel(
    const __half* __restrict__ eh, float* __restrict__ attn,
    const float* __restrict__ inv)
{
    const int row  = blockIdx.x * 8 + (threadIdx.x >> 5);
    const int lane = threadIdx.x & 31;
    const float s = inv[row];
    const uint2* src = (const uint2*)(eh + (long long)row * PL);
    float4* dst = (float4*)(attn + (long long)row * PL);
    #pragma unroll
    for (int i = 0; i < 16; i++){
        uint2 u = src[i*32 + lane];
        __half2 h0 = *(__half2*)&u.x, h1 = *(__half2*)&u.y;
        float2 f0 = __half22float2(h0), f1 = __half22float2(h1);
        float4 v = {f0.x*s, f0.y*s, f1.x*s, f1.y*s};
        dst[i*32 + lane] = v;
    }
}

// ---------------------------------------------------------------------------
// FP16 GEMM: C[M][N] = A[M][K] @ Bt[N][K]^T (+bias). 128x128 tile, BK=32,
// cp.async double buffer, 256 threads, 2 CTAs/SM.
// MODE 0: C float out. MODE 1: QKV scatter (q/k row-major, v transposed).
// ---------------------------------------------------------------------------
template<int MODE>
__global__ void __launch_bounds__(256, 2) gemm_fp16(
    const __half* __restrict__ A, const __half* __restrict__ Bt,
    const float* __restrict__ bias, float* __restrict__ C,
    int N, int K,
    __half* __restrict__ qd, __half* __restrict__ kd, __half* __restrict__ vd)
{
    __shared__ __half As[2][128][40];
    __shared__ __half Bs[2][128][40];
    const int tid = threadIdx.x, lane = tid & 31, warp = tid >> 5;
    const int wm = warp >> 2, wn = warp & 3;          // 2 x 4 warps
    const int g = lane >> 2, t4 = lane & 3;
    const int row0 = blockIdx.y * 128, col0 = blockIdx.x * 128;
    float acc[4][4][4] = {};

    const int iters = K / 32;
    #pragma unroll
    for (int p = 0; p < 2; p++){
        int idx = tid + p*256; int r = idx >> 2, ch = (idx & 3) << 3;
        CP16(smem_u32(&As[0][r][ch]), &A[(long long)(row0+r)*K + ch]);
        CP16(smem_u32(&Bs[0][r][ch]), &Bt[(long long)(col0+r)*K + ch]);
    }
    CP_COMMIT();
    for (int it = 0; it < iters; ++it){
        if (it + 1 < iters){
            const int k0 = (it+1)*32, nb = (it+1)&1;
            #pragma unroll
            for (int p = 0; p < 2; p++){
                int idx = tid + p*256; int r = idx >> 2, ch = (idx & 3) << 3;
                CP16(smem_u32(&As[nb][r][ch]), &A[(long long)(row0+r)*K + k0 + ch]);
                CP16(smem_u32(&Bs[nb][r][ch]), &Bt[(long long)(col0+r)*K + k0 + ch]);
            }
        }
        CP_COMMIT();
        CP_WAIT1();
        __syncthreads();
        const int b = it & 1;
        #pragma unroll
        for (int ks = 0; ks < 2; ks++){
            unsigned af[4][4], bf[4][2];
            #pragma unroll
            for (int mt = 0; mt < 4; mt++){
                int r = wm*64 + mt*16 + g;
                af[mt][0] = *(unsigned*)&As[b][r  ][ks*16 + t4*2    ];
                af[mt][1] = *(unsigned*)&As[b][r+8][ks*16 + t4*2    ];
                af[mt][2] = *(unsigned*)&As[b][r  ][ks*16 + t4*2 + 8];
                af[mt][3] = *(unsigned*)&As[b][r+8][ks*16 + t4*2 + 8];
            }
            #pragma unroll
            for (int nt = 0; nt < 4; nt++){
                int c = wn*32 + nt*8 + g;
                bf[nt][0] = *(unsigned*)&Bs[b][c][ks*16 + t4*2    ];
                bf[nt][1] = *(unsigned*)&Bs[b][c][ks*16 + t4*2 + 8];
            }
            #pragma unroll
            for (int mt = 0; mt < 4; mt++)
                #pragma unroll
                for (int nt = 0; nt < 4; nt++)
                    mma16(acc[mt][nt], af[mt], bf[nt]);
        }
        __syncthreads();
    }
    #pragma unroll
    for (int mt = 0; mt < 4; mt++){
        #pragma unroll
        for (int nt = 0; nt < 4; nt++){
            const int r = row0 + wm*64 + mt*16 + g;
            const int c = col0 + wn*32 + nt*8 + t4*2;
            float bx = bias ? bias[c] : 0.f, by = bias ? bias[c+1] : 0.f;
            float v0 = acc[mt][nt][0] + bx, v1 = acc[mt][nt][1] + by;
            float v2 = acc[mt][nt][2] + bx, v3 = acc[mt][nt][3] + by;
            if (MODE == 0){
                float2 o0 = {v0, v1}, o1 = {v2, v3};
                *(float2*)&C[(long long)r*N + c]     = o0;
                *(float2*)&C[(long long)(r+8)*N + c] = o1;
            } else {
                const int sel = c >> 10, cd = c & 1023;
                const int d = cd & 63, csl = cd >> 6;
                #pragma unroll
                for (int hh = 0; hh < 2; hh++){
                    const int rr = r + hh*8;
                    const float a0 = hh ? v2 : v0, a1 = hh ? v3 : v1;
                    const int bb = rr >> 11, lrow = rr & 2047;
                    const int z = bb*16 + (lrow >> 7);
                    const int l2 = (lrow & 127)*16 + csl;
                    if (sel == 2){
                        vd[((long long)z*PHD + d    )*PL + l2] = __float2half(a0);
                        vd[((long long)z*PHD + d + 1)*PL + l2] = __float2half(a1);
                    } else {
                        __half* dst = sel == 0 ? qd : kd;
                        long long off = ((long long)z*PL + l2)*PHD + d;
                        *(unsigned*)&dst[off] = h2u(__floats2half2_rn(a0, a1));
                    }
                }
            }
        }
    }
}

// ---------------------------------------------------------------------------
// SINGLE-PASS fp16 flash attention; unnormalized e written as fp16 to g_eh.
// Grid (PL/128, PZH), 256 threads, 2 CTAs/SM.
// smem (halves): Qs[128][72] | Ks[64][72] | Vs[64][72] | Ps[128][72]
// ---------------------------------------------------------------------------
__global__ void __launch_bounds__(256, 2) flash1_attn(
    const __half* __restrict__ Qg, const __half* __restrict__ Kg,
    const __half* __restrict__ Vtg, const float* __restrict__ mask,
    __half* __restrict__ eh, __half* __restrict__ ctx,
    float* __restrict__ invg)
{
    extern __shared__ __half smh[];
    __half* Qs = smh;                 // 128*72
    __half* Ks = smh + 9216;          // 64*72
    __half* Vs = smh + 13824;         // 64*72
    __half* Ps = smh + 18432;         // 128*72
    __shared__ float srs[128];

    const int z = blockIdx.y, row0 = blockIdx.x * 128;
    Qg  += (long long)z * PL * PHD;
    Kg  += (long long)z * PL * PHD;
    Vtg += (long long)z * PHD * PL;   // [d][l]
    eh  += (long long)z * PL * PL;

    const int tid = threadIdx.x, lane = tid & 31, warp = tid >> 5;
    const int wq = warp >> 1, wn = warp & 1;   // 4 row-strips x 2 col-strips
    const int g = lane >> 2, t4 = lane & 3;
    const float scale = 0.03125f;

    #pragma unroll
    for (int p = 0; p < 4; p++){
        int idx = tid + p*256; int r = idx >> 3, ch = (idx & 7) << 3;
        CP16(smem_u32(&Qs[r*72 + ch]), &Qg[(long long)(row0+r)*PHD + ch]);
    }
    #pragma unroll
    for (int p = 0; p < 2; p++){
        int idx = tid + p*256; int r = idx >> 3, ch = (idx & 7) << 3;
        CP16(smem_u32(&Ks[r*72 + ch]), &Kg[(long long)r*PHD + ch]);
        CP16(smem_u32(&Vs[r*72 + ch]), &Vtg[(long long)r*PL + ch]);
    }
    CP_COMMIT();
    if (tid < 128) srs[tid] = 0.f;

    float acc[2][4][4] = {};     // unnormalized ctx
    float rs[2][2] = {};         // running row sums

    for (int j = 0; j < PL/64; ++j){
        CP_WAIT0();
        __syncthreads();
        // ---- S = Q @ K^T ----
        float acc1[2][4][4] = {};
        #pragma unroll
        for (int ks = 0; ks < 4; ks++){
            unsigned af[2][4], bf[4][2];
            #pragma unroll
            for (int mt = 0; mt < 2; mt++){
                int rq = wq*32 + mt*16 + g;
                af[mt][0] = *(unsigned*)&Qs[rq*72     + ks*16 + t4*2    ];
                af[mt][1] = *(unsigned*)&Qs[(rq+8)*72 + ks*16 + t4*2    ];
                af[mt][2] = *(unsigned*)&Qs[rq*72     + ks*16 + t4*2 + 8];
                af[mt][3] = *(unsigned*)&Qs[(rq+8)*72 + ks*16 + t4*2 + 8];
            }
            #pragma unroll
            for (int nt = 0; nt < 4; nt++){
                int kn = wn*32 + nt*8 + g;
                bf[nt][0] = *(unsigned*)&Ks[kn*72 + ks*16 + t4*2    ];
                bf[nt][1] = *(unsigned*)&Ks[kn*72 + ks*16 + t4*2 + 8];
            }
            #pragma unroll
            for (int mt = 0; mt < 2; mt++)
                #pragma unroll
                for (int nt = 0; nt < 4; nt++)
                    mma16(acc1[mt][nt], af[mt], bf[nt]);
        }
        __syncthreads();
        if (j + 1 < PL/64){
            const __half* Kn = Kg + (long long)(j+1)*64*PHD;
            #pragma unroll
            for (int p = 0; p < 2; p++){
                int idx = tid + p*256; int r = idx >> 3, ch = (idx & 7) << 3;
                CP16(smem_u32(&Ks[r*72 + ch]), &Kn[(long long)r*PHD + ch]);
            }
            CP_COMMIT();
        }
        // ---- e = exp(scale*S*mask): fp16 write to eh, row sums, stage P
        #pragma unroll
        for (int mt = 0; mt < 2; mt++){
            const int rq = wq*32 + mt*16 + g;
            const int qr = row0 + rq;
            #pragma unroll
            for (int nt = 0; nt < 4; nt++){
                const int cc = wn*32 + nt*8 + t4*2;
                const int kc = j*64 + cc;
                float2 m0 = *(const float2*)&mask[(long long)qr*PL + kc];
                float2 m1 = *(const float2*)&mask[(long long)(qr+8)*PL + kc];
                float e0 = __expf(acc1[mt][nt][0]*scale*m0.x);
                float e1 = __expf(acc1[mt][nt][1]*scale*m0.y);
                float e2 = __expf(acc1[mt][nt][2]*scale*m1.x);
                float e3 = __expf(acc1[mt][nt][3]*scale*m1.y);
                rs[mt][0] += e0 + e1;
                rs[mt][1] += e2 + e3;
                unsigned u0 = h2u(__floats2half2_rn(e0, e1));
                unsigned u1 = h2u(__floats2half2_rn(e2, e3));
                *(unsigned*)&eh[(long long)qr*PL + kc]     = u0;
                *(unsigned*)&eh[(long long)(qr+8)*PL + kc] = u1;
                *(unsigned*)&Ps[rq*72 + cc]     = u0;
                *(unsigned*)&Ps[(rq+8)*72 + cc] = u1;
            }
        }
        __syncthreads();
        // ---- ctx += P @ V ----
        #pragma unroll
        for (int ks = 0; ks < 4; ks++){
            unsigned af[2][4], bf[4][2];
            #pragma unroll
            for (int mt = 0; mt < 2; mt++){
                int rq = wq*32 + mt*16 + g;
                af[mt][0] = *(unsigned*)&Ps[rq*72     + ks*16 + t4*2    ];
                af[mt][1] = *(unsigned*)&Ps[(rq+8)*72 + ks*16 + t4*2    ];
                af[mt][2] = *(unsigned*)&Ps[rq*72     + ks*16 + t4*2 + 8];
                af[mt][3] = *(unsigned*)&Ps[(rq+8)*72 + ks*16 + t4*2 + 8];
            }
            #pragma unroll
            for (int nt = 0; nt < 4; nt++){
                int cn = wn*32 + nt*8 + g;
                bf[nt][0] = *(unsigned*)&Vs[cn*72 + ks*16 + t4*2    ];
                bf[nt][1] = *(unsigned*)&Vs[cn*72 + ks*16 + t4*2 + 8];
            }
            #pragma unroll
            for (int mt = 0; mt < 2; mt++)
                #pragma unroll
                for (int nt = 0; nt < 4; nt++)
                    mma16(acc[mt][nt], af[mt], bf[nt]);
        }
        __syncthreads();
        if (j + 1 < PL/64){
            const __half* Vn = Vtg + (long long)(j+1)*64;
            #pragma unroll
            for (int p = 0; p < 2; p++){
                int idx = tid + p*256; int r = idx >> 3, ch = (idx & 7) << 3;
                CP16(smem_u32(&Vs[r*72 + ch]), &Vn[(long long)r*PL + ch]);
            }
            CP_COMMIT();
        }
    }
    // ---- reduce row sums ----
    #pragma unroll
    for (int mt = 0; mt < 2; mt++)
        #pragma unroll
        for (int hh = 0; hh < 2; hh++){
            rs[mt][hh] += __shfl_xor_sync(0xffffffffu, rs[mt][hh], 1);
            rs[mt][hh] += __shfl_xor_sync(0xffffffffu, rs[mt][hh], 2);
        }
    if (t4 == 0){
        #pragma unroll
        for (int mt = 0; mt < 2; mt++){
            const int lr = wq*32 + mt*16 + g;
            atomicAdd(&srs[lr],   rs[mt][0]);
            atomicAdd(&srs[lr+8], rs[mt][1]);
        }
    }
    __syncthreads();
    if (tid < 128) invg[z*PL + row0 + tid] = 1.f / srs[tid];
    // ---- epilogue: ctx*inv as fp16, merged [B,L,D] layout ----
    const int bb = z >> 4, h = z & 15;
    #pragma unroll
    for (int mt = 0; mt < 2; mt++){
        const int lr = wq*32 + mt*16 + g;
        const float inv0 = 1.f / srs[lr];
        const float inv1 = 1.f / srs[lr+8];
        #pragma unroll
        for (int nt = 0; nt < 4; nt++){
            const int d = wn*32 + nt*8 + t4*2;
            {
                const int l = row0 + lr;
                int crow = bb*PL + h*128 + (l >> 4);
                int ccol = (l & 15)*64 + d;
                *(unsigned*)&ctx[(long long)crow*PD + ccol] =
                    h2u(__floats2half2_rn(acc[mt][nt][0]*inv0, acc[mt][nt][1]*inv0));
            }
            {
                const int l = row0 + lr + 8;
                int crow = bb*PL + h*128 + (l >> 4);
                int ccol = (l & 15)*64 + d;
                *(unsigned*)&ctx[(long long)crow*PD + ccol] =
                    h2u(__floats2half2_rn(acc[mt][nt][2]*inv1, acc[mt][nt][3]*inv1));
            }
        }
    }
}

// ---------------------------------------------------------------------------
extern "C" void kernel_launch(void* const* d_in, const int* in_sizes, int n_in,
                              void* d_out, int out_size)
{
    const float* x    = (const float*)d_in[0];
    const float* mask = (const float*)d_in[1];
    const float* Wqkv = (const float*)d_in[2];
    const float* bqkv = (const float*)d_in[3];
    const float* Wout = (const float*)d_in[4];
    const float* bout = (const float*)d_in[5];
    float* out = (float*)d_out;

    __half *xh, *wqkvt, *woutt, *q, *k, *vt, *ctx, *eh; float* invg;
    cudaGetSymbolAddress((void**)&xh,    g_xh);
    cudaGetSymbolAddress((void**)&wqkvt, g_wqkvt);
    cudaGetSymbolAddress((void**)&woutt, g_woutt);
    cudaGetSymbolAddress((void**)&q,     g_q);
    cudaGetSymbolAddress((void**)&k,     g_k);
    cudaGetSymbolAddress((void**)&vt,    g_vt);
    cudaGetSymbolAddress((void**)&ctx,   g_ctx);
    cudaGetSymbolAddress((void**)&eh,    g_eh);
    cudaGetSymbolAddress((void**)&invg,  g_inv);

    float* attn = out + OUT_ELEMS;   // attn lives in d_out after out

    // 0) convert inputs to fp16 (weights transposed to [N][K])
    cvt_fp16_kernel<<<(PM*PD/4+255)/256, 256>>>((const float4*)x, (uint2*)xh, PM*PD/4);
    {
        dim3 gt(PN3/32, PD/32);
        cvt_transpose_kernel<<<gt, 256>>>(Wqkv, wqkvt, PD, PN3);
    }
    {
        dim3 gt(PD/32, PD/32);
        cvt_transpose_kernel<<<gt, 256>>>(Wout, woutt, PD, PD);
    }

    // 1) QKV projection + head split (q/k row-major, v transposed per head)
    {
        dim3 grd(PN3/128, PM/128);
        gemm_fp16<1><<<grd, 256>>>(xh, wqkvt, bqkv, nullptr, PN3, PD,
                                   q, k, vt);
    }
    // 2) single-pass flash: unnormalized e (fp16) + ctx + row sums
    {
        const int smem_bytes = 27648 * 2;   // 55296 B
        cudaFuncSetAttribute(flash1_attn,
                             cudaFuncAttributeMaxDynamicSharedMemorySize,
                             smem_bytes);
        dim3 gf(PL/128, PZH);
        flash1_attn<<<gf, 256, smem_bytes>>>(q, k, vt, mask, eh, ctx, invg);
    }
    // 3) output projection
    {
        dim3 grd(PD/128, PM/128);
        gemm_fp16<0><<<grd, 256>>>(ctx, woutt, bout, out, PD, PD,
                                   nullptr, nullptr, nullptr);
    }
    // 4) expand-normalize attn: fp16 -> fp32 with 1/rowsum
    norm_attn_kernel<<<PZH*PL/8, 256>>>(eh, attn, invg);
}